// round 1
// baseline (speedup 1.0000x reference)
#include <cuda_runtime.h>
#include <cuda_bf16.h>
#include <math.h>

// Problem constants
#define B_  2
#define L_  256
#define C_  256
#define H_  1024          // 4*C
#define NB_ 64
#define NTOK (B_*L_*L_)   // 131072
#define LN_EPS 1e-5f

// Tiling
#define TM 64             // tokens per block
#define NCHUNK 128        // fc1 output columns per chunk (8 chunks)
#define KTILE 64

// Scratch (device globals: no cudaMalloc allowed)
__device__ float g_mod[B_][3*C_];     // shift | scale | gate per batch
__device__ int   g_idx[NTOK];

// ---------------------------------------------------------------------------
// Kernel 1: adaLN modulation  mod = silu(c) @ ada_w.T + ada_b
// grid 6 x 256
__global__ void mod_kernel(const float* __restrict__ c_BD,
                           const float* __restrict__ ada_w,
                           const float* __restrict__ ada_b) {
    __shared__ float sc[C_];
    int b  = blockIdx.x / 3;
    int oo = (blockIdx.x % 3) * 256 + threadIdx.x;   // 0..767
    float cv = c_BD[b*C_ + threadIdx.x];
    sc[threadIdx.x] = cv / (1.0f + expf(-cv));
    __syncthreads();
    const float* wr = ada_w + oo*C_;
    float s = 0.0f;
    #pragma unroll 8
    for (int k = 0; k < C_; ++k) s = fmaf(sc[k], wr[k], s);
    g_mod[b][oo] = s + ada_b[oo];
}

// ---------------------------------------------------------------------------
// Kernel 2: distance buckets  idx = searchsorted(bins, ||xi-xj||^2, left)
// grid 512 x 256
__global__ void idx_kernel(const float* __restrict__ x,
                           const float* __restrict__ bins) {
    __shared__ float bs[NB_-1];
    if (threadIdx.x < NB_-1) bs[threadIdx.x] = bins[threadIdx.x];
    __syncthreads();
    int t = blockIdx.x * 256 + threadIdx.x;
    int b = t >> 16, rem = t & 65535, i = rem >> 8, j = rem & 255;
    const float* xi = x + (b*L_ + i)*3;
    const float* xj = x + (b*L_ + j)*3;
    // match CPU two-rounding exactly: no FMA contraction here
    float t0 = __fadd_rn(xi[0], -xj[0]);
    float t1 = __fadd_rn(xi[1], -xj[1]);
    float t2 = __fadd_rn(xi[2], -xj[2]);
    float d  = __fadd_rn(__fadd_rn(__fmul_rn(t0,t0), __fmul_rn(t1,t1)),
                         __fmul_rn(t2,t2));
    int cnt = 0;
    #pragma unroll
    for (int k = 0; k < NB_-1; ++k) cnt += (bs[k] < d) ? 1 : 0;
    g_idx[t] = cnt;
}

// ---------------------------------------------------------------------------
// Main fused kernel: per 64-token tile
//   s = embed[idx] + pos[rel];  s = s*(1+scale)+shift;  h = LN(s)
//   h1 = gelu(h @ W1^T + b1);   h2 = h1 @ W2^T + b2;    out = s + gate*h2
//
// Shared memory layout (floats):
//   s_ln [64][256]                 @ 0        (16384)
//   w1s  [64 k][128 n]             @ 16384    ( 8192)  k-major for float4 reads
//   h1s  [64 m][128 n]             @ 24576    ( 8192)
//   w2s  [256 c][64 n] XOR-swizzle @ 32768    (16384)
//   shs/scs/gts/lgs/lbs [256] each @ 49152    ( 1280)
#define SM_W1  16384
#define SM_H1  24576
#define SM_W2  32768
#define SM_PAR 49152
#define SMEM_FLOATS (SM_PAR + 5*256)
#define SMEM_BYTES  (SMEM_FLOATS * 4)

__device__ __forceinline__ float gelu_exact(float x) {
    return 0.5f * x * (1.0f + erff(x * 0.70710678118654752440f));
}

__global__ __launch_bounds__(256, 1)
void main_kernel(const float* __restrict__ emb,
                 const float* __restrict__ pos,
                 const float* __restrict__ lng,
                 const float* __restrict__ lnb,
                 const float* __restrict__ w1,
                 const float* __restrict__ b1,
                 const float* __restrict__ w2,
                 const float* __restrict__ b2,
                 float* __restrict__ out) {
    extern __shared__ float smem[];
    float* s_ln = smem;
    float* w1s  = smem + SM_W1;
    float* h1s  = smem + SM_H1;
    float* w2s  = smem + SM_W2;
    float* shs  = smem + SM_PAR;
    float* scs  = shs + 256;
    float* gts  = scs + 256;
    float* lgs  = gts + 256;
    float* lbs  = lgs + 256;

    const int tid  = threadIdx.x;
    const int lane = tid & 31;
    const int warp = tid >> 5;
    const int tc   = lane;             // c-block / n-block lane id

    const int t0 = blockIdx.x * TM;
    const int b  = t0 >> 16;
    const int ii = (t0 >> 8) & 255;
    const int j0 = t0 & 255;

    // parameters
    shs[tid] = g_mod[b][tid];
    scs[tid] = g_mod[b][256 + tid];
    gts[tid] = g_mod[b][512 + tid];
    lgs[tid] = lng[tid];
    lbs[tid] = lnb[tid];
    __syncthreads();

    // ---- Phase 1: build s (modulated) + LayerNorm into s_ln --------------
    // warp w handles tokens m = w*8 .. w*8+7 ; lane handles c = lane+32q
    for (int r = 0; r < 8; ++r) {
        int m   = (warp << 3) + r;
        int t   = t0 + m;
        int idv = g_idx[t];
        int rel = ii - (j0 + m);
        rel = rel < -64 ? -64 : (rel > 63 ? 63 : rel);
        rel += 64;
        const float* er = emb + (idv << 8);
        const float* pr = pos + (rel << 8);
        float v[8];
        float sum = 0.0f;
        #pragma unroll
        for (int q = 0; q < 8; ++q) {
            int c = lane + (q << 5);
            float s = er[c] + pr[c];
            s = fmaf(s, 1.0f + scs[c], shs[c]);
            v[q] = s;
            sum += s;
        }
        #pragma unroll
        for (int off = 16; off; off >>= 1)
            sum += __shfl_xor_sync(0xffffffffu, sum, off);
        float mu = sum * (1.0f / 256.0f);
        float sq = 0.0f;
        #pragma unroll
        for (int q = 0; q < 8; ++q) { float d = v[q] - mu; sq = fmaf(d, d, sq); }
        #pragma unroll
        for (int off = 16; off; off >>= 1)
            sq += __shfl_xor_sync(0xffffffffu, sq, off);
        float rstd = rsqrtf(sq * (1.0f / 256.0f) + LN_EPS);
        #pragma unroll
        for (int q = 0; q < 8; ++q) {
            int c = lane + (q << 5);
            s_ln[m*256 + c] = fmaf((v[q] - mu) * rstd, lgs[c], lbs[c]);
        }
    }
    __syncthreads();

    // ---- Main loop: fused fc1 -> gelu -> fc2, accumulate acc[m][c] -------
    float acc[8][8];
    #pragma unroll
    for (int a = 0; a < 8; ++a)
        #pragma unroll
        for (int bb = 0; bb < 8; ++bb) acc[a][bb] = 0.0f;

    for (int nc = 0; nc < H_/NCHUNK; ++nc) {          // 8 chunks of 128
        const int nbase = nc * NCHUNK;
        float c1[8][4];
        #pragma unroll
        for (int a = 0; a < 8; ++a)
            #pragma unroll
            for (int bb = 0; bb < 4; ++bb) c1[a][bb] = 0.0f;

        // GEMM1: H1[64m, 128n] = s_ln[64m,256k] . W1[128n,256k]^T
        for (int kt = 0; kt < 4; ++kt) {              // k tiles of 64
            __syncthreads();
            {   // load W1 tile transposed to k-major [64k][128n]
                int n  = tid & 127;
                int kh = tid >> 7;                    // 0/1
                const float* wp = w1 + (nbase + n)*C_ + kt*KTILE + kh*32;
                #pragma unroll
                for (int q = 0; q < 8; ++q) {
                    float4 wv = *(const float4*)(wp + (q << 2));
                    int kk = kh*32 + (q << 2);
                    w1s[(kk+0)*128 + n] = wv.x;
                    w1s[(kk+1)*128 + n] = wv.y;
                    w1s[(kk+2)*128 + n] = wv.z;
                    w1s[(kk+3)*128 + n] = wv.w;
                }
            }
            __syncthreads();
            const float* sp = s_ln + (warp << 3)*256 + kt*KTILE;
            #pragma unroll 4
            for (int k = 0; k < KTILE; ++k) {
                float4 b4 = *(const float4*)(w1s + k*128 + (tc << 2));
                #pragma unroll
                for (int i2 = 0; i2 < 8; ++i2) {
                    float a = sp[i2*256 + k];
                    c1[i2][0] = fmaf(a, b4.x, c1[i2][0]);
                    c1[i2][1] = fmaf(a, b4.y, c1[i2][1]);
                    c1[i2][2] = fmaf(a, b4.z, c1[i2][2]);
                    c1[i2][3] = fmaf(a, b4.w, c1[i2][3]);
                }
            }
        }
        // bias + gelu -> h1s
        {
            float4 bb1 = *(const float4*)(b1 + nbase + (tc << 2));
            #pragma unroll
            for (int i2 = 0; i2 < 8; ++i2) {
                int m = (warp << 3) + i2;
                float4 hv;
                hv.x = gelu_exact(c1[i2][0] + bb1.x);
                hv.y = gelu_exact(c1[i2][1] + bb1.y);
                hv.z = gelu_exact(c1[i2][2] + bb1.z);
                hv.w = gelu_exact(c1[i2][3] + bb1.w);
                *(float4*)(h1s + m*128 + (tc << 2)) = hv;
            }
        }
        __syncthreads();

        // GEMM2: acc[64m,256c] += gelu(H1)[64m,128n] . W2[256c, nchunk]^T
        for (int ns = 0; ns < 2; ++ns) {              // 64-n sub tiles
            __syncthreads();
            {   // load W2 sub tile [256c][64n], XOR swizzle on 4-float groups
                int within = tid & 15;
                int crow   = tid >> 4;
                #pragma unroll 4
                for (int p = 0; p < 16; ++p) {
                    int c = (p << 4) + crow;
                    float4 wv = *(const float4*)(w2 + c*H_ + nbase + ns*64 + (within << 2));
                    int col = within ^ ((c >> 3) & 15);
                    *(float4*)(w2s + (c << 6) + (col << 2)) = wv;
                }
            }
            __syncthreads();
            #pragma unroll 2
            for (int n4 = 0; n4 < 16; ++n4) {
                int nloc = ns*64 + (n4 << 2);
                float4 a4[8];
                #pragma unroll
                for (int i2 = 0; i2 < 8; ++i2)
                    a4[i2] = *(const float4*)(h1s + ((warp << 3) + i2)*128 + nloc);
                int col4 = ((n4 ^ (tc & 15)) << 2);
                #pragma unroll
                for (int j = 0; j < 8; ++j) {
                    float4 w4 = *(const float4*)(w2s + (((tc << 3) + j) << 6) + col4);
                    #pragma unroll
                    for (int i2 = 0; i2 < 8; ++i2) {
                        acc[i2][j] = fmaf(a4[i2].x, w4.x, acc[i2][j]);
                        acc[i2][j] = fmaf(a4[i2].y, w4.y, acc[i2][j]);
                        acc[i2][j] = fmaf(a4[i2].z, w4.z, acc[i2][j]);
                        acc[i2][j] = fmaf(a4[i2].w, w4.w, acc[i2][j]);
                    }
                }
            }
        }
    }

    // ---- Epilogue: out = s + gate * (acc + b2) ---------------------------
    const int c0 = tc << 3;
    float4 sc0 = *(float4*)(scs + c0), sc1 = *(float4*)(scs + c0 + 4);
    float4 sh0 = *(float4*)(shs + c0), sh1 = *(float4*)(shs + c0 + 4);
    float4 g0  = *(float4*)(gts + c0), g1  = *(float4*)(gts + c0 + 4);
    float4 bb0 = *(const float4*)(b2 + c0), bb1 = *(const float4*)(b2 + c0 + 4);

    #pragma unroll
    for (int i2 = 0; i2 < 8; ++i2) {
        int m   = (warp << 3) + i2;
        int t   = t0 + m;
        int idv = g_idx[t];
        int rel = ii - (j0 + m);
        rel = rel < -64 ? -64 : (rel > 63 ? 63 : rel);
        rel += 64;
        const float4* er = (const float4*)(emb + (idv << 8) + c0);
        const float4* pr = (const float4*)(pos + (rel << 8) + c0);
        float4 e0 = er[0], e1 = er[1];
        float4 p0 = pr[0], p1 = pr[1];
        float4 o0, o1;
        {
            float s;
            s = fmaf(e0.x + p0.x, 1.0f + sc0.x, sh0.x); o0.x = fmaf(g0.x, acc[i2][0] + bb0.x, s);
            s = fmaf(e0.y + p0.y, 1.0f + sc0.y, sh0.y); o0.y = fmaf(g0.y, acc[i2][1] + bb0.y, s);
            s = fmaf(e0.z + p0.z, 1.0f + sc0.z, sh0.z); o0.z = fmaf(g0.z, acc[i2][2] + bb0.z, s);
            s = fmaf(e0.w + p0.w, 1.0f + sc0.w, sh0.w); o0.w = fmaf(g0.w, acc[i2][3] + bb0.w, s);
            s = fmaf(e1.x + p1.x, 1.0f + sc1.x, sh1.x); o1.x = fmaf(g1.x, acc[i2][4] + bb1.x, s);
            s = fmaf(e1.y + p1.y, 1.0f + sc1.y, sh1.y); o1.y = fmaf(g1.y, acc[i2][5] + bb1.y, s);
            s = fmaf(e1.z + p1.z, 1.0f + sc1.z, sh1.z); o1.z = fmaf(g1.z, acc[i2][6] + bb1.z, s);
            s = fmaf(e1.w + p1.w, 1.0f + sc1.w, sh1.w); o1.w = fmaf(g1.w, acc[i2][7] + bb1.w, s);
        }
        float4* op = (float4*)(out + t*256 + c0);
        op[0] = o0;
        op[1] = o1;
    }
}

// ---------------------------------------------------------------------------
extern "C" void kernel_launch(void* const* d_in, const int* in_sizes, int n_in,
                              void* d_out, int out_size) {
    const float* x     = (const float*)d_in[0];
    const float* c_BD  = (const float*)d_in[1];
    const float* emb   = (const float*)d_in[2];
    const float* pos   = (const float*)d_in[3];
    const float* bins  = (const float*)d_in[4];
    const float* ada_w = (const float*)d_in[5];
    const float* ada_b = (const float*)d_in[6];
    const float* ln_g  = (const float*)d_in[7];
    const float* ln_b  = (const float*)d_in[8];
    const float* fc1_w = (const float*)d_in[9];
    const float* fc1_b = (const float*)d_in[10];
    const float* fc2_w = (const float*)d_in[11];
    const float* fc2_b = (const float*)d_in[12];
    float* out = (float*)d_out;

    cudaFuncSetAttribute(main_kernel,
                         cudaFuncAttributeMaxDynamicSharedMemorySize, SMEM_BYTES);

    mod_kernel<<<6, 256>>>(c_BD, ada_w, ada_b);
    idx_kernel<<<NTOK/256, 256>>>(x, bins);
    main_kernel<<<NTOK/TM, 256, SMEM_BYTES>>>(emb, pos, ln_g, ln_b,
                                              fc1_w, fc1_b, fc2_w, fc2_b, out);
}

// round 2
// speedup vs baseline: 1.0006x; 1.0006x over previous
#include <cuda_runtime.h>
#include <cuda_bf16.h>
#include <math.h>

// Problem constants
#define B_  2
#define L_  256
#define C_  256
#define H_  1024          // 4*C
#define NB_ 64
#define NTOK (B_*L_*L_)   // 131072
#define LN_EPS 1e-5f

// Tiling
#define TM 64             // tokens per block
#define NCHUNK 128        // fc1 output columns per chunk (8 chunks)
#define KTILE 64

// Scratch (device globals: no cudaMalloc allowed)
__device__ float g_mod[B_][3*C_];     // shift | scale | gate per batch
__device__ int   g_idx[NTOK];

// ---------------------------------------------------------------------------
// Kernel 1: adaLN modulation  mod = silu(c) @ ada_w.T + ada_b
// grid 6 x 256
__global__ void mod_kernel(const float* __restrict__ c_BD,
                           const float* __restrict__ ada_w,
                           const float* __restrict__ ada_b) {
    __shared__ float sc[C_];
    int b  = blockIdx.x / 3;
    int oo = (blockIdx.x % 3) * 256 + threadIdx.x;   // 0..767
    float cv = c_BD[b*C_ + threadIdx.x];
    sc[threadIdx.x] = cv / (1.0f + expf(-cv));
    __syncthreads();
    const float* wr = ada_w + oo*C_;
    float s = 0.0f;
    #pragma unroll 8
    for (int k = 0; k < C_; ++k) s = fmaf(sc[k], wr[k], s);
    g_mod[b][oo] = s + ada_b[oo];
}

// ---------------------------------------------------------------------------
// Kernel 2: distance buckets  idx = searchsorted(bins, ||xi-xj||^2, left)
// grid 512 x 256
__global__ void idx_kernel(const float* __restrict__ x,
                           const float* __restrict__ bins) {
    __shared__ float bs[NB_-1];
    if (threadIdx.x < NB_-1) bs[threadIdx.x] = bins[threadIdx.x];
    __syncthreads();
    int t = blockIdx.x * 256 + threadIdx.x;
    int b = t >> 16, rem = t & 65535, i = rem >> 8, j = rem & 255;
    const float* xi = x + (b*L_ + i)*3;
    const float* xj = x + (b*L_ + j)*3;
    // match CPU two-rounding exactly: no FMA contraction here
    float t0 = __fadd_rn(xi[0], -xj[0]);
    float t1 = __fadd_rn(xi[1], -xj[1]);
    float t2 = __fadd_rn(xi[2], -xj[2]);
    float d  = __fadd_rn(__fadd_rn(__fmul_rn(t0,t0), __fmul_rn(t1,t1)),
                         __fmul_rn(t2,t2));
    int cnt = 0;
    #pragma unroll
    for (int k = 0; k < NB_-1; ++k) cnt += (bs[k] < d) ? 1 : 0;
    g_idx[t] = cnt;
}

// ---------------------------------------------------------------------------
// Main fused kernel: per 64-token tile
//   s = embed[idx] + pos[rel];  s = s*(1+scale)+shift;  h = LN(s)
//   h1 = gelu(h @ W1^T + b1);   h2 = h1 @ W2^T + b2;    out = s + gate*h2
//
// Shared memory layout (floats):
//   s_ln [64][256]                 @ 0        (16384)
//   w1s  [64 k][128 n]             @ 16384    ( 8192)  k-major for float4 reads
//   h1s  [64 m][128 n]             @ 24576    ( 8192)
//   w2s  [256 c][64 n] XOR-swizzle @ 32768    (16384)
//   shs/scs/gts/lgs/lbs [256] each @ 49152    ( 1280)
#define SM_W1  16384
#define SM_H1  24576
#define SM_W2  32768
#define SM_PAR 49152
#define SMEM_FLOATS (SM_PAR + 5*256)
#define SMEM_BYTES  (SMEM_FLOATS * 4)

__device__ __forceinline__ float gelu_exact(float x) {
    return 0.5f * x * (1.0f + erff(x * 0.70710678118654752440f));
}

__global__ __launch_bounds__(256, 1)
void main_kernel(const float* __restrict__ emb,
                 const float* __restrict__ pos,
                 const float* __restrict__ lng,
                 const float* __restrict__ lnb,
                 const float* __restrict__ w1,
                 const float* __restrict__ b1,
                 const float* __restrict__ w2,
                 const float* __restrict__ b2,
                 float* __restrict__ out) {
    extern __shared__ float smem[];
    float* s_ln = smem;
    float* w1s  = smem + SM_W1;
    float* h1s  = smem + SM_H1;
    float* w2s  = smem + SM_W2;
    float* shs  = smem + SM_PAR;
    float* scs  = shs + 256;
    float* gts  = scs + 256;
    float* lgs  = gts + 256;
    float* lbs  = lgs + 256;

    const int tid  = threadIdx.x;
    const int lane = tid & 31;
    const int warp = tid >> 5;
    const int tc   = lane;             // c-block / n-block lane id

    const int t0 = blockIdx.x * TM;
    const int b  = t0 >> 16;
    const int ii = (t0 >> 8) & 255;
    const int j0 = t0 & 255;

    // parameters
    shs[tid] = g_mod[b][tid];
    scs[tid] = g_mod[b][256 + tid];
    gts[tid] = g_mod[b][512 + tid];
    lgs[tid] = lng[tid];
    lbs[tid] = lnb[tid];
    __syncthreads();

    // ---- Phase 1: build s (modulated) + LayerNorm into s_ln --------------
    // warp w handles tokens m = w*8 .. w*8+7 ; lane handles c = lane+32q
    for (int r = 0; r < 8; ++r) {
        int m   = (warp << 3) + r;
        int t   = t0 + m;
        int idv = g_idx[t];
        int rel = ii - (j0 + m);
        rel = rel < -64 ? -64 : (rel > 63 ? 63 : rel);
        rel += 64;
        const float* er = emb + (idv << 8);
        const float* pr = pos + (rel << 8);
        float v[8];
        float sum = 0.0f;
        #pragma unroll
        for (int q = 0; q < 8; ++q) {
            int c = lane + (q << 5);
            float s = er[c] + pr[c];
            s = fmaf(s, 1.0f + scs[c], shs[c]);
            v[q] = s;
            sum += s;
        }
        #pragma unroll
        for (int off = 16; off; off >>= 1)
            sum += __shfl_xor_sync(0xffffffffu, sum, off);
        float mu = sum * (1.0f / 256.0f);
        float sq = 0.0f;
        #pragma unroll
        for (int q = 0; q < 8; ++q) { float d = v[q] - mu; sq = fmaf(d, d, sq); }
        #pragma unroll
        for (int off = 16; off; off >>= 1)
            sq += __shfl_xor_sync(0xffffffffu, sq, off);
        float rstd = rsqrtf(sq * (1.0f / 256.0f) + LN_EPS);
        #pragma unroll
        for (int q = 0; q < 8; ++q) {
            int c = lane + (q << 5);
            s_ln[m*256 + c] = fmaf((v[q] - mu) * rstd, lgs[c], lbs[c]);
        }
    }
    __syncthreads();

    // ---- Main loop: fused fc1 -> gelu -> fc2, accumulate acc[m][c] -------
    float acc[8][8];
    #pragma unroll
    for (int a = 0; a < 8; ++a)
        #pragma unroll
        for (int bb = 0; bb < 8; ++bb) acc[a][bb] = 0.0f;

    for (int nc = 0; nc < H_/NCHUNK; ++nc) {          // 8 chunks of 128
        const int nbase = nc * NCHUNK;
        float c1[8][4];
        #pragma unroll
        for (int a = 0; a < 8; ++a)
            #pragma unroll
            for (int bb = 0; bb < 4; ++bb) c1[a][bb] = 0.0f;

        // GEMM1: H1[64m, 128n] = s_ln[64m,256k] . W1[128n,256k]^T
        for (int kt = 0; kt < 4; ++kt) {              // k tiles of 64
            __syncthreads();
            {   // load W1 tile transposed to k-major [64k][128n]
                int n  = tid & 127;
                int kh = tid >> 7;                    // 0/1
                const float* wp = w1 + (nbase + n)*C_ + kt*KTILE + kh*32;
                #pragma unroll
                for (int q = 0; q < 8; ++q) {
                    float4 wv = *(const float4*)(wp + (q << 2));
                    int kk = kh*32 + (q << 2);
                    w1s[(kk+0)*128 + n] = wv.x;
                    w1s[(kk+1)*128 + n] = wv.y;
                    w1s[(kk+2)*128 + n] = wv.z;
                    w1s[(kk+3)*128 + n] = wv.w;
                }
            }
            __syncthreads();
            const float* sp = s_ln + (warp << 3)*256 + kt*KTILE;
            #pragma unroll 4
            for (int k = 0; k < KTILE; ++k) {
                float4 b4 = *(const float4*)(w1s + k*128 + (tc << 2));
                #pragma unroll
                for (int i2 = 0; i2 < 8; ++i2) {
                    float a = sp[i2*256 + k];
                    c1[i2][0] = fmaf(a, b4.x, c1[i2][0]);
                    c1[i2][1] = fmaf(a, b4.y, c1[i2][1]);
                    c1[i2][2] = fmaf(a, b4.z, c1[i2][2]);
                    c1[i2][3] = fmaf(a, b4.w, c1[i2][3]);
                }
            }
        }
        // bias + gelu -> h1s
        {
            float4 bb1 = *(const float4*)(b1 + nbase + (tc << 2));
            #pragma unroll
            for (int i2 = 0; i2 < 8; ++i2) {
                int m = (warp << 3) + i2;
                float4 hv;
                hv.x = gelu_exact(c1[i2][0] + bb1.x);
                hv.y = gelu_exact(c1[i2][1] + bb1.y);
                hv.z = gelu_exact(c1[i2][2] + bb1.z);
                hv.w = gelu_exact(c1[i2][3] + bb1.w);
                *(float4*)(h1s + m*128 + (tc << 2)) = hv;
            }
        }
        __syncthreads();

        // GEMM2: acc[64m,256c] += gelu(H1)[64m,128n] . W2[256c, nchunk]^T
        for (int ns = 0; ns < 2; ++ns) {              // 64-n sub tiles
            __syncthreads();
            {   // load W2 sub tile [256c][64n], XOR swizzle on 4-float groups
                int within = tid & 15;
                int crow   = tid >> 4;
                #pragma unroll 4
                for (int p = 0; p < 16; ++p) {
                    int c = (p << 4) + crow;
                    float4 wv = *(const float4*)(w2 + c*H_ + nbase + ns*64 + (within << 2));
                    int col = within ^ ((c >> 3) & 15);
                    *(float4*)(w2s + (c << 6) + (col << 2)) = wv;
                }
            }
            __syncthreads();
            #pragma unroll 2
            for (int n4 = 0; n4 < 16; ++n4) {
                int nloc = ns*64 + (n4 << 2);
                float4 a4[8];
                #pragma unroll
                for (int i2 = 0; i2 < 8; ++i2)
                    a4[i2] = *(const float4*)(h1s + ((warp << 3) + i2)*128 + nloc);
                int col4 = ((n4 ^ (tc & 15)) << 2);
                #pragma unroll
                for (int j = 0; j < 8; ++j) {
                    float4 w4 = *(const float4*)(w2s + (((tc << 3) + j) << 6) + col4);
                    #pragma unroll
                    for (int i2 = 0; i2 < 8; ++i2) {
                        acc[i2][j] = fmaf(a4[i2].x, w4.x, acc[i2][j]);
                        acc[i2][j] = fmaf(a4[i2].y, w4.y, acc[i2][j]);
                        acc[i2][j] = fmaf(a4[i2].z, w4.z, acc[i2][j]);
                        acc[i2][j] = fmaf(a4[i2].w, w4.w, acc[i2][j]);
                    }
                }
            }
        }
    }

    // ---- Epilogue: out = s + gate * (acc + b2) ---------------------------
    const int c0 = tc << 3;
    float4 sc0 = *(float4*)(scs + c0), sc1 = *(float4*)(scs + c0 + 4);
    float4 sh0 = *(float4*)(shs + c0), sh1 = *(float4*)(shs + c0 + 4);
    float4 g0  = *(float4*)(gts + c0), g1  = *(float4*)(gts + c0 + 4);
    float4 bb0 = *(const float4*)(b2 + c0), bb1 = *(const float4*)(b2 + c0 + 4);

    #pragma unroll
    for (int i2 = 0; i2 < 8; ++i2) {
        int m   = (warp << 3) + i2;
        int t   = t0 + m;
        int idv = g_idx[t];
        int rel = ii - (j0 + m);
        rel = rel < -64 ? -64 : (rel > 63 ? 63 : rel);
        rel += 64;
        const float4* er = (const float4*)(emb + (idv << 8) + c0);
        const float4* pr = (const float4*)(pos + (rel << 8) + c0);
        float4 e0 = er[0], e1 = er[1];
        float4 p0 = pr[0], p1 = pr[1];
        float4 o0, o1;
        {
            float s;
            s = fmaf(e0.x + p0.x, 1.0f + sc0.x, sh0.x); o0.x = fmaf(g0.x, acc[i2][0] + bb0.x, s);
            s = fmaf(e0.y + p0.y, 1.0f + sc0.y, sh0.y); o0.y = fmaf(g0.y, acc[i2][1] + bb0.y, s);
            s = fmaf(e0.z + p0.z, 1.0f + sc0.z, sh0.z); o0.z = fmaf(g0.z, acc[i2][2] + bb0.z, s);
            s = fmaf(e0.w + p0.w, 1.0f + sc0.w, sh0.w); o0.w = fmaf(g0.w, acc[i2][3] + bb0.w, s);
            s = fmaf(e1.x + p1.x, 1.0f + sc1.x, sh1.x); o1.x = fmaf(g1.x, acc[i2][4] + bb1.x, s);
            s = fmaf(e1.y + p1.y, 1.0f + sc1.y, sh1.y); o1.y = fmaf(g1.y, acc[i2][5] + bb1.y, s);
            s = fmaf(e1.z + p1.z, 1.0f + sc1.z, sh1.z); o1.z = fmaf(g1.z, acc[i2][6] + bb1.z, s);
            s = fmaf(e1.w + p1.w, 1.0f + sc1.w, sh1.w); o1.w = fmaf(g1.w, acc[i2][7] + bb1.w, s);
        }
        float4* op = (float4*)(out + t*256 + c0);
        op[0] = o0;
        op[1] = o1;
    }
}

// ---------------------------------------------------------------------------
extern "C" void kernel_launch(void* const* d_in, const int* in_sizes, int n_in,
                              void* d_out, int out_size) {
    const float* x     = (const float*)d_in[0];
    const float* c_BD  = (const float*)d_in[1];
    const float* emb   = (const float*)d_in[2];
    const float* pos   = (const float*)d_in[3];
    const float* bins  = (const float*)d_in[4];
    const float* ada_w = (const float*)d_in[5];
    const float* ada_b = (const float*)d_in[6];
    const float* ln_g  = (const float*)d_in[7];
    const float* ln_b  = (const float*)d_in[8];
    const float* fc1_w = (const float*)d_in[9];
    const float* fc1_b = (const float*)d_in[10];
    const float* fc2_w = (const float*)d_in[11];
    const float* fc2_b = (const float*)d_in[12];
    float* out = (float*)d_out;

    cudaFuncSetAttribute(main_kernel,
                         cudaFuncAttributeMaxDynamicSharedMemorySize, SMEM_BYTES);

    mod_kernel<<<6, 256>>>(c_BD, ada_w, ada_b);
    idx_kernel<<<NTOK/256, 256>>>(x, bins);
    main_kernel<<<NTOK/TM, 256, SMEM_BYTES>>>(emb, pos, ln_g, ln_b,
                                              fc1_w, fc1_b, fc2_w, fc2_b, out);
}

// round 5
// speedup vs baseline: 2.8016x; 2.7998x over previous
#include <cuda_runtime.h>
#include <cuda_bf16.h>
#include <math.h>
#include <stdint.h>

// Problem constants
#define B_  2
#define L_  256
#define C_  256
#define NTOK (B_*L_*L_)
#define LN_EPS 1e-5f
#define TM 64            // tokens per CTA

// ---------------------------------------------------------------------------
// Device scratch (no cudaMalloc allowed)
__device__ __align__(16) float g_mod[B_][3*C_];
// W1 split-bf16, SW128 tiles: [nc(8)][kt(4)][plane(2)] of [128n x 64k] (16KB)
__device__ __align__(16) unsigned char g_w1[1048576];
// W2 split-bf16, SW128 tiles: [nc(8)][kt(2)][plane(2)] of [256c x 64k] (32KB)
__device__ __align__(16) unsigned char g_w2[1048576];

#define SWZ(o) ((o) ^ (((o)>>3)&0x70))

// ---------------------------------------------------------------------------
__device__ __forceinline__ uint32_t smem_u32(const void* p){
    uint32_t a;
    asm("{ .reg .u64 t; cvta.to.shared.u64 t, %1; cvt.u32.u64 %0, t; }"
        : "=r"(a) : "l"(p));
    return a;
}
#define MBAR_INIT(a,c) \
    asm volatile("mbarrier.init.shared.b64 [%0], %1;" :: "r"(a), "r"(c) : "memory")
#define MBAR_INVAL(a) \
    asm volatile("mbarrier.inval.shared.b64 [%0];" :: "r"(a) : "memory")
#define MBAR_EXPECT(a,tx) \
    asm volatile("mbarrier.arrive.expect_tx.shared.b64 _, [%0], %1;" :: "r"(a), "r"(tx) : "memory")
#define MBAR_WAIT(mb, ph) do{                                                   \
    uint32_t _m=(mb), _p=(ph), _d;                                              \
    asm volatile("{\n\t.reg .pred p;\n\t"                                       \
      "mbarrier.try_wait.parity.acquire.cta.shared::cta.b64 p, [%1], %2;\n\t"   \
      "selp.b32 %0,1,0,p;\n\t}" : "=r"(_d) : "r"(_m), "r"(_p) : "memory");      \
    while(!_d){                                                                 \
      asm volatile("{\n\t.reg .pred p;\n\t"                                     \
        "mbarrier.try_wait.parity.acquire.cta.shared::cta.b64 p, [%1], %2, 0x989680;\n\t" \
        "selp.b32 %0,1,0,p;\n\t}" : "=r"(_d) : "r"(_m), "r"(_p) : "memory"); }  \
}while(0)

__device__ __forceinline__ void bulk_g2s(uint32_t dst, const void* src,
                                         uint32_t bytes, uint32_t mbar){
    asm volatile("cp.async.bulk.shared::cluster.global.mbarrier::complete_tx::bytes "
                 "[%0], [%1], %2, [%3];"
                 :: "r"(dst), "l"(src), "r"(bytes), "r"(mbar) : "memory");
}

__device__ __forceinline__ void ldsm4(uint32_t* r, uint32_t a){
    asm volatile("ldmatrix.sync.aligned.m8n8.x4.shared.b16 {%0,%1,%2,%3}, [%4];"
        : "=r"(r[0]),"=r"(r[1]),"=r"(r[2]),"=r"(r[3]) : "r"(a));
}
__device__ __forceinline__ void ldsm2(uint32_t* r, uint32_t a){
    asm volatile("ldmatrix.sync.aligned.m8n8.x2.shared.b16 {%0,%1}, [%2];"
        : "=r"(r[0]),"=r"(r[1]) : "r"(a));
}
__device__ __forceinline__ void mma_bf16(float* c, const uint32_t* a, const uint32_t* b){
    asm volatile("mma.sync.aligned.m16n8k16.row.col.f32.bf16.bf16.f32 "
        "{%0,%1,%2,%3}, {%4,%5,%6,%7}, {%8,%9}, {%0,%1,%2,%3};"
        : "+f"(c[0]),"+f"(c[1]),"+f"(c[2]),"+f"(c[3])
        : "r"(a[0]),"r"(a[1]),"r"(a[2]),"r"(a[3]), "r"(b[0]),"r"(b[1]));
}

// swizzled row addressing (byte offsets)
__device__ __forceinline__ uint32_t sw_row128(int row, int kb){  // 128B rows
    return (uint32_t)(row*128 + (kb ^ ((row & 7) << 4)));
}
__device__ __forceinline__ uint32_t sw_rowA(int m, int kb){      // 512B rows
    return (uint32_t)(m*512 + ((kb & ~127) | ((kb & 127) ^ ((m & 7) << 4))));
}
__device__ __forceinline__ uint32_t sw_rowH(int m, int kb){      // 256B rows
    return (uint32_t)(m*256 + ((kb & ~127) | ((kb & 127) ^ ((m & 7) << 4))));
}

// split fp32 pair -> (hi,lo) packed bf16x2
__device__ __forceinline__ void split2(float a, float b, uint32_t& hi, uint32_t& lo){
    __nv_bfloat16 ha = __float2bfloat16(a);
    __nv_bfloat16 hb = __float2bfloat16(b);
    float ra = a - __bfloat162float(ha);
    float rb = b - __bfloat162float(hb);
    __nv_bfloat16 la = __float2bfloat16(ra);
    __nv_bfloat16 lb = __float2bfloat16(rb);
    hi = ((uint32_t)__bfloat16_as_ushort(hb) << 16) | __bfloat16_as_ushort(ha);
    lo = ((uint32_t)__bfloat16_as_ushort(lb) << 16) | __bfloat16_as_ushort(la);
}
__device__ __forceinline__ float gelu_exact(float x){
    return 0.5f * x * (1.0f + erff(x * 0.70710678118654752440f));
}

// ---------------------------------------------------------------------------
// Weight prep: fp32 -> split-bf16, SW128 K-major tiles
__global__ void prep_w1(const float* __restrict__ w1){
    int n = blockIdx.x;            // 0..1023
    int k = threadIdx.x;           // 0..255
    float v = w1[n*256 + k];
    __nv_bfloat16 h = __float2bfloat16(v);
    __nv_bfloat16 l = __float2bfloat16(v - __bfloat162float(h));
    int nc = n >> 7, nl = n & 127, kt = k >> 6, kk = k & 63;
    size_t tbase = (size_t)((nc*4 + kt)*2) * 16384u;
    uint32_t off = SWZ((uint32_t)(nl*128 + kk*2));
    *(__nv_bfloat16*)(g_w1 + tbase + off)         = h;
    *(__nv_bfloat16*)(g_w1 + tbase + 16384 + off) = l;
}
__global__ void prep_w2(const float* __restrict__ w2){
    int c = blockIdx.x;            // 0..255
    #pragma unroll
    for (int q = 0; q < 4; ++q){
        int k = threadIdx.x + q*256;   // 0..1023
        float v = w2[c*1024 + k];
        __nv_bfloat16 h = __float2bfloat16(v);
        __nv_bfloat16 l = __float2bfloat16(v - __bfloat162float(h));
        int nc = k >> 7, kt = (k >> 6) & 1, kk = k & 63;
        size_t tbase = (size_t)((nc*2 + kt)*2) * 32768u;
        uint32_t off = SWZ((uint32_t)(c*128 + kk*2));
        *(__nv_bfloat16*)(g_w2 + tbase + off)         = h;
        *(__nv_bfloat16*)(g_w2 + tbase + 32768 + off) = l;
    }
}

// ---------------------------------------------------------------------------
// adaLN modulation: mod = silu(c) @ ada_w.T + ada_b
__global__ void mod_kernel(const float* __restrict__ c_BD,
                           const float* __restrict__ ada_w,
                           const float* __restrict__ ada_b){
    __shared__ float sc[C_];
    int b   = blockIdx.x / 12;
    int grp = blockIdx.x % 12;
    int tid = threadIdx.x;
    float cv = c_BD[b*C_ + tid];
    sc[tid] = cv / (1.0f + expf(-cv));
    __syncthreads();
    int oo = grp*64 + (tid >> 2);
    int k0 = (tid & 3) * 64;
    const float* wr = ada_w + oo*C_ + k0;
    const float* ss = sc + k0;
    float s = 0.0f;
    #pragma unroll 8
    for (int k = 0; k < 64; ++k) s = fmaf(ss[k], wr[k], s);
    s += __shfl_xor_sync(0xffffffffu, s, 1);
    s += __shfl_xor_sync(0xffffffffu, s, 2);
    if ((tid & 3) == 0) g_mod[b][oo] = s + ada_b[oo];
}

// ---------------------------------------------------------------------------
// SMEM layout (bytes)
#define OFF_A    0u         // Ahi [64m x 512B]
#define OFF_ALO  32768u     // Alo
#define OFF_W1   65536u     // 2 x 16KB stage buffers
#define OFF_H1   98304u     // Hhi [64m x 256B]
#define OFF_H1LO 114688u
#define OFF_W2   131072u    // 2 x 32KB stage buffers
#define OFF_B1S  196608u    // fc1 bias (4KB)
#define OFF_PAR  200704u    // shift|scale|gate|b2 (4KB)
#define OFF_IDX  204800u    // int[64]
#define OFF_MB   205056u    // 4 mbarriers
#define SMEM_BYTES 205088u

#define ISSUE_W1(sg, buf) do{ int _nc=(sg)>>3, _s=(sg)&7, _kt=_s>>1, _p=_s&1;   \
    MBAR_EXPECT(sb+OFF_MB+(uint32_t)(buf)*8u, 16384u);                          \
    bulk_g2s(sb+OFF_W1+(uint32_t)(buf)*16384u,                                  \
             g_w1 + (size_t)((_nc*4+_kt)*2+_p)*16384u, 16384u,                  \
             sb+OFF_MB+(uint32_t)(buf)*8u); }while(0)
#define ISSUE_W2(jg, buf) do{ int _nc=(jg)>>2, _j=(jg)&3, _kt=_j>>1, _p=_j&1;   \
    MBAR_EXPECT(sb+OFF_MB+16u+(uint32_t)(buf)*8u, 32768u);                      \
    bulk_g2s(sb+OFF_W2+(uint32_t)(buf)*32768u,                                  \
             g_w2 + (size_t)((_nc*2+_kt)*2+_p)*32768u, 32768u,                  \
             sb+OFF_MB+16u+(uint32_t)(buf)*8u); }while(0)

__global__ __launch_bounds__(256, 1)
void main_kernel(const float* __restrict__ x,
                 const float* __restrict__ bins,
                 const float* __restrict__ emb,
                 const float* __restrict__ pos,
                 const float* __restrict__ lng,
                 const float* __restrict__ lnb,
                 const float* __restrict__ b1,
                 const float* __restrict__ b2,
                 float* __restrict__ out){
    extern __shared__ __align__(1024) unsigned char smp[];
    const uint32_t sb = smem_u32(smp);
    const int tid  = threadIdx.x;
    const int warp = tid >> 5;
    const int lane = tid & 31;
    const int g    = lane >> 2;       // mma group row
    const int tg   = lane & 3;        // thread-in-group
    const int wm   = warp & 1;        // 2 warps in m
    const int wn   = warp >> 1;       // 4 warps in n

    const int t0 = blockIdx.x * TM;
    const int b  = t0 >> 16;
    const int ii = (t0 >> 8) & 255;
    const int j0 = t0 & 255;

    int*   idxs = (int*)(smp + OFF_IDX);
    float* b1s  = (float*)(smp + OFF_B1S);
    float* shs  = (float*)(smp + OFF_PAR);
    float* scs  = shs + 256;
    float* gts  = scs + 256;
    float* b2s  = gts + 256;

    if (tid == 0){
        MBAR_INIT(sb+OFF_MB+0u, 1);
        MBAR_INIT(sb+OFF_MB+8u, 1);
        MBAR_INIT(sb+OFF_MB+16u, 1);
        MBAR_INIT(sb+OFF_MB+24u, 1);
    }
    __syncthreads();
    if (tid == 0){
        ISSUE_W1(0, 0);
        ISSUE_W1(1, 1);
        ISSUE_W2(0, 0);
        ISSUE_W2(1, 1);
    }

    // param smem copies
    shs[tid] = g_mod[b][tid];
    scs[tid] = g_mod[b][256 + tid];
    gts[tid] = g_mod[b][512 + tid];
    b2s[tid] = b2[tid];
    #pragma unroll
    for (int q = 0; q < 4; ++q) b1s[tid + q*256] = b1[tid + q*256];

    // distance buckets for this tile's 64 tokens
    if (tid < TM){
        int j = j0 + tid;
        const float* xi = x + (b*L_ + ii)*3;
        const float* xj = x + (b*L_ + j )*3;
        float d0 = __fadd_rn(xi[0], -xj[0]);
        float d1 = __fadd_rn(xi[1], -xj[1]);
        float d2v = __fadd_rn(xi[2], -xj[2]);
        float d  = __fadd_rn(__fadd_rn(__fmul_rn(d0,d0), __fmul_rn(d1,d1)),
                             __fmul_rn(d2v,d2v));
        int cnt = 0;
        #pragma unroll
        for (int k = 0; k < 63; ++k) cnt += (bins[k] < d) ? 1 : 0;
        idxs[tid] = cnt;
    }
    __syncthreads();

    // ---- Phase 0: s -> modulate -> LN -> split bf16 into A ---------------
    for (int r = 0; r < 8; ++r){
        int m = warp*8 + r;
        int idv = idxs[m];
        int rel = ii - (j0 + m);
        rel = rel < -64 ? -64 : (rel > 63 ? 63 : rel);
        rel += 64;
        const float2* er = (const float2*)(emb + (idv << 8));
        const float2* pr = (const float2*)(pos + (rel << 8));
        float vx[4], vy[4];
        float sum = 0.0f;
        #pragma unroll
        for (int q = 0; q < 4; ++q){
            int c0 = 2*lane + 64*q;
            float2 e = er[c0 >> 1];
            float2 p = pr[c0 >> 1];
            float a0 = fmaf(e.x + p.x, 1.0f + scs[c0],   shs[c0]);
            float a1 = fmaf(e.y + p.y, 1.0f + scs[c0+1], shs[c0+1]);
            vx[q] = a0; vy[q] = a1;
            sum += a0 + a1;
        }
        #pragma unroll
        for (int off = 16; off; off >>= 1)
            sum += __shfl_xor_sync(0xffffffffu, sum, off);
        float mu = sum * (1.0f/256.0f);
        float sq = 0.0f;
        #pragma unroll
        for (int q = 0; q < 4; ++q){
            float a0 = vx[q]-mu, a1 = vy[q]-mu;
            sq = fmaf(a0,a0, fmaf(a1,a1, sq));
        }
        #pragma unroll
        for (int off = 16; off; off >>= 1)
            sq += __shfl_xor_sync(0xffffffffu, sq, off);
        float rstd = rsqrtf(sq * (1.0f/256.0f) + LN_EPS);
        #pragma unroll
        for (int q = 0; q < 4; ++q){
            int c0 = 2*lane + 64*q;
            float h0 = fmaf((vx[q]-mu)*rstd, lng[c0],   lnb[c0]);
            float h1 = fmaf((vy[q]-mu)*rstd, lng[c0+1], lnb[c0+1]);
            uint32_t hp, lp;
            split2(h0, h1, hp, lp);
            uint32_t so = sw_rowA(m, 2*c0);
            *(uint32_t*)(smp + OFF_A   + so) = hp;
            *(uint32_t*)(smp + OFF_ALO + so) = lp;
        }
    }
    __syncthreads();

    float d2[2][8][4];
    #pragma unroll
    for (int a=0;a<2;++a)
        #pragma unroll
        for (int bb=0;bb<8;++bb)
            #pragma unroll
            for (int c=0;c<4;++c) d2[a][bb][c] = 0.0f;

    int nextW1 = 2, nextW2 = 2;
    int phW1_0 = 0, phW1_1 = 0, phW2_0 = 0, phW2_1 = 0;

    for (int nc = 0; nc < 8; ++nc){
        float c1[2][4][4];
        #pragma unroll
        for (int a=0;a<2;++a)
            #pragma unroll
            for (int bb=0;bb<4;++bb)
                #pragma unroll
                for (int c=0;c<4;++c) c1[a][bb][c] = 0.0f;

        // ---- GEMM1: 8 plane-stages of W1 ---------------------------------
        #pragma unroll 1
        for (int s = 0; s < 8; ++s){
            const int kt = s >> 1, p = s & 1, buf = s & 1;
            if (buf == 0){ MBAR_WAIT(sb+OFF_MB+0u, phW1_0); phW1_0 ^= 1; }
            else         { MBAR_WAIT(sb+OFF_MB+8u, phW1_1); phW1_1 ^= 1; }
            const uint32_t wb = sb + OFF_W1 + (uint32_t)buf*16384u;
            #pragma unroll
            for (int k4 = 0; k4 < 4; ++k4){
                const int kbW = k4*32 + ((lane>>3)&1)*16;
                const int kbA = kt*128 + k4*32 + (lane>>4)*16;
                uint32_t Bf[4][2];
                #pragma unroll
                for (int nt = 0; nt < 4; ++nt)
                    ldsm2(Bf[nt], wb + sw_row128(wn*32 + nt*8 + (lane&7), kbW));
                #pragma unroll
                for (int mt = 0; mt < 2; ++mt){
                    const int mrow = wm*32 + mt*16 + (lane&15);
                    uint32_t Af[4];
                    ldsm4(Af, sb + OFF_A + sw_rowA(mrow, kbA));
                    #pragma unroll
                    for (int nt = 0; nt < 4; ++nt) mma_bf16(c1[mt][nt], Af, Bf[nt]);
                    if (p == 0){
                        ldsm4(Af, sb + OFF_ALO + sw_rowA(mrow, kbA));
                        #pragma unroll
                        for (int nt = 0; nt < 4; ++nt) mma_bf16(c1[mt][nt], Af, Bf[nt]);
                    }
                }
            }
            __syncthreads();
            if (tid == 0 && nextW1 < 64){ ISSUE_W1(nextW1, buf); }
            nextW1++;
        }

        // ---- epilogue1: bias + gelu -> split -> H1 -----------------------
        #pragma unroll
        for (int mt = 0; mt < 2; ++mt){
            #pragma unroll
            for (int nt = 0; nt < 4; ++nt){
                const int ncol = wn*32 + nt*8 + 2*tg;
                const float bb0 = b1s[nc*128 + ncol];
                const float bb1 = b1s[nc*128 + ncol + 1];
                #pragma unroll
                for (int half = 0; half < 2; ++half){
                    const int m = wm*32 + mt*16 + g + half*8;
                    float f0 = gelu_exact(c1[mt][nt][half*2+0] + bb0);
                    float f1 = gelu_exact(c1[mt][nt][half*2+1] + bb1);
                    uint32_t hp, lp;
                    split2(f0, f1, hp, lp);
                    uint32_t so = sw_rowH(m, 2*ncol);
                    *(uint32_t*)(smp + OFF_H1   + so) = hp;
                    *(uint32_t*)(smp + OFF_H1LO + so) = lp;
                }
            }
        }
        __syncthreads();

        // ---- GEMM2: 4 plane-stages of W2 ---------------------------------
        #pragma unroll 1
        for (int j = 0; j < 4; ++j){
            const int kt2 = j >> 1, p = j & 1, buf = j & 1;
            if (buf == 0){ MBAR_WAIT(sb+OFF_MB+16u, phW2_0); phW2_0 ^= 1; }
            else         { MBAR_WAIT(sb+OFF_MB+24u, phW2_1); phW2_1 ^= 1; }
            const uint32_t wb = sb + OFF_W2 + (uint32_t)buf*32768u;
            #pragma unroll
            for (int k4 = 0; k4 < 4; ++k4){
                const int kbW = k4*32 + ((lane>>3)&1)*16;
                const int kbH = kt2*128 + k4*32 + (lane>>4)*16;
                uint32_t Bf[8][2];
                #pragma unroll
                for (int nt = 0; nt < 8; ++nt)
                    ldsm2(Bf[nt], wb + sw_row128(wn*64 + nt*8 + (lane&7), kbW));
                #pragma unroll
                for (int mt = 0; mt < 2; ++mt){
                    const int mrow = wm*32 + mt*16 + (lane&15);
                    uint32_t Hf[4];
                    ldsm4(Hf, sb + OFF_H1 + sw_rowH(mrow, kbH));
                    #pragma unroll
                    for (int nt = 0; nt < 8; ++nt) mma_bf16(d2[mt][nt], Hf, Bf[nt]);
                    if (p == 0){
                        ldsm4(Hf, sb + OFF_H1LO + sw_rowH(mrow, kbH));
                        #pragma unroll
                        for (int nt = 0; nt < 8; ++nt) mma_bf16(d2[mt][nt], Hf, Bf[nt]);
                    }
                }
            }
            __syncthreads();
            if (tid == 0 && nextW2 < 32){ ISSUE_W2(nextW2, buf); }
            nextW2++;
        }
    }

    // ---- final epilogue: out = s + gate * (D2 + b2) ----------------------
    #pragma unroll
    for (int mt = 0; mt < 2; ++mt){
        #pragma unroll
        for (int half = 0; half < 2; ++half){
            const int m = wm*32 + mt*16 + g + half*8;
            const int t = t0 + m;
            const int idv = idxs[m];
            int rel = ii - (j0 + m);
            rel = rel < -64 ? -64 : (rel > 63 ? 63 : rel);
            rel += 64;
            const float* er = emb + (idv << 8);
            const float* pr = pos + (rel << 8);
            #pragma unroll
            for (int nt = 0; nt < 8; ++nt){
                const int c = wn*64 + nt*8 + 2*tg;
                float v0 = d2[mt][nt][half*2+0];
                float v1 = d2[mt][nt][half*2+1];
                float2 e2 = *(const float2*)(er + c);
                float2 p2 = *(const float2*)(pr + c);
                float s0 = fmaf(e2.x + p2.x, 1.0f + scs[c],   shs[c]);
                float s1 = fmaf(e2.y + p2.y, 1.0f + scs[c+1], shs[c+1]);
                float2 o;
                o.x = fmaf(gts[c],   v0 + b2s[c],   s0);
                o.y = fmaf(gts[c+1], v1 + b2s[c+1], s1);
                *(float2*)(out + (size_t)t*256 + c) = o;
            }
        }
    }
    __syncthreads();
    if (tid == 0){
        MBAR_INVAL(sb+OFF_MB+0u);
        MBAR_INVAL(sb+OFF_MB+8u);
        MBAR_INVAL(sb+OFF_MB+16u);
        MBAR_INVAL(sb+OFF_MB+24u);
    }
}

// ---------------------------------------------------------------------------
extern "C" void kernel_launch(void* const* d_in, const int* in_sizes, int n_in,
                              void* d_out, int out_size) {
    const float* x     = (const float*)d_in[0];
    const float* c_BD  = (const float*)d_in[1];
    const float* emb   = (const float*)d_in[2];
    const float* pos   = (const float*)d_in[3];
    const float* bins  = (const float*)d_in[4];
    const float* ada_w = (const float*)d_in[5];
    const float* ada_b = (const float*)d_in[6];
    const float* ln_g  = (const float*)d_in[7];
    const float* ln_b  = (const float*)d_in[8];
    const float* fc1_w = (const float*)d_in[9];
    const float* fc1_b = (const float*)d_in[10];
    const float* fc2_w = (const float*)d_in[11];
    const float* fc2_b = (const float*)d_in[12];
    float* out = (float*)d_out;

    static bool attr_set = false;
    if (!attr_set){
        cudaFuncSetAttribute(main_kernel,
                             cudaFuncAttributeMaxDynamicSharedMemorySize, SMEM_BYTES);
        attr_set = true;
    }

    prep_w1<<<1024, 256>>>(fc1_w);
    prep_w2<<<256, 256>>>(fc2_w);
    mod_kernel<<<24, 256>>>(c_BD, ada_w, ada_b);
    main_kernel<<<NTOK/TM, 256, SMEM_BYTES>>>(x, bins, emb, pos, ln_g, ln_b,
                                              fc1_b, fc2_b, out);
}

// round 6
// speedup vs baseline: 3.1442x; 1.1223x over previous
#include <cuda_runtime.h>
#include <cuda_bf16.h>
#include <math.h>
#include <stdint.h>

// Problem constants
#define B_  2
#define L_  256
#define C_  256
#define NTOK (B_*L_*L_)
#define LN_EPS 1e-5f
#define TM 64            // tokens per CTA

// ---------------------------------------------------------------------------
// Device scratch (no cudaMalloc allowed)
__device__ __align__(16) float g_mod[B_][3*C_];
// W1 split-bf16, SW128: stage s=nc*4+kt -> 32KB {hi 16KB, lo 16KB}, [128n x 64k]
__device__ __align__(16) unsigned char g_w1[1048576];
// W2 split-bf16, SW128: stage s=nc*4+j  -> 32KB one plane, [256c x 64k]
__device__ __align__(16) unsigned char g_w2[1048576];

#define SWZ(o) ((o) ^ (((o)>>3)&0x70))

// ---------------------------------------------------------------------------
__device__ __forceinline__ uint32_t smem_u32(const void* p){
    uint32_t a;
    asm("{ .reg .u64 t; cvta.to.shared.u64 t, %1; cvt.u32.u64 %0, t; }"
        : "=r"(a) : "l"(p));
    return a;
}
#define MBAR_INIT(a,c) \
    asm volatile("mbarrier.init.shared.b64 [%0], %1;" :: "r"(a), "r"(c) : "memory")
#define MBAR_INVAL(a) \
    asm volatile("mbarrier.inval.shared.b64 [%0];" :: "r"(a) : "memory")
#define MBAR_EXPECT(a,tx) \
    asm volatile("mbarrier.arrive.expect_tx.shared.b64 _, [%0], %1;" :: "r"(a), "r"(tx) : "memory")
#define MBAR_ARRIVE(a) \
    asm volatile("mbarrier.arrive.shared.b64 _, [%0];" :: "r"(a) : "memory")
#define MBAR_WAIT(mb, ph) do{                                                   \
    uint32_t _m=(mb), _p=(ph), _d;                                              \
    asm volatile("{\n\t.reg .pred p;\n\t"                                       \
      "mbarrier.try_wait.parity.acquire.cta.shared::cta.b64 p, [%1], %2;\n\t"   \
      "selp.b32 %0,1,0,p;\n\t}" : "=r"(_d) : "r"(_m), "r"(_p) : "memory");      \
    while(!_d){                                                                 \
      asm volatile("{\n\t.reg .pred p;\n\t"                                     \
        "mbarrier.try_wait.parity.acquire.cta.shared::cta.b64 p, [%1], %2, 0x989680;\n\t" \
        "selp.b32 %0,1,0,p;\n\t}" : "=r"(_d) : "r"(_m), "r"(_p) : "memory"); }  \
}while(0)
#define BARW(id) asm volatile("bar.sync %0, 128;" :: "r"(id) : "memory")

__device__ __forceinline__ void bulk_g2s(uint32_t dst, const void* src,
                                         uint32_t bytes, uint32_t mbar){
    asm volatile("cp.async.bulk.shared::cluster.global.mbarrier::complete_tx::bytes "
                 "[%0], [%1], %2, [%3];"
                 :: "r"(dst), "l"(src), "r"(bytes), "r"(mbar) : "memory");
}

__device__ __forceinline__ void ldsm4(uint32_t* r, uint32_t a){
    asm volatile("ldmatrix.sync.aligned.m8n8.x4.shared.b16 {%0,%1,%2,%3}, [%4];"
        : "=r"(r[0]),"=r"(r[1]),"=r"(r[2]),"=r"(r[3]) : "r"(a));
}
__device__ __forceinline__ void mma_bf16(float* c, const uint32_t* a, const uint32_t* b){
    asm volatile("mma.sync.aligned.m16n8k16.row.col.f32.bf16.bf16.f32 "
        "{%0,%1,%2,%3}, {%4,%5,%6,%7}, {%8,%9}, {%0,%1,%2,%3};"
        : "+f"(c[0]),"+f"(c[1]),"+f"(c[2]),"+f"(c[3])
        : "r"(a[0]),"r"(a[1]),"r"(a[2]),"r"(a[3]), "r"(b[0]),"r"(b[1]));
}

// swizzled row addressing (byte offsets)
__device__ __forceinline__ uint32_t sw_row128(int row, int kb){  // 128B rows
    return (uint32_t)(row*128 + (kb ^ ((row & 7) << 4)));
}
__device__ __forceinline__ uint32_t sw_rowA(int m, int kb){      // 512B rows
    return (uint32_t)(m*512 + ((kb & ~127) | ((kb & 127) ^ ((m & 7) << 4))));
}
__device__ __forceinline__ uint32_t sw_rowH(int m, int kb){      // 256B rows
    return (uint32_t)(m*256 + ((kb & ~127) | ((kb & 127) ^ ((m & 7) << 4))));
}

// split fp32 pair -> (hi,lo) packed bf16x2
__device__ __forceinline__ void split2(float a, float b, uint32_t& hi, uint32_t& lo){
    __nv_bfloat16 ha = __float2bfloat16(a);
    __nv_bfloat16 hb = __float2bfloat16(b);
    float ra = a - __bfloat162float(ha);
    float rb = b - __bfloat162float(hb);
    __nv_bfloat16 la = __float2bfloat16(ra);
    __nv_bfloat16 lb = __float2bfloat16(rb);
    hi = ((uint32_t)__bfloat16_as_ushort(hb) << 16) | __bfloat16_as_ushort(ha);
    lo = ((uint32_t)__bfloat16_as_ushort(lb) << 16) | __bfloat16_as_ushort(la);
}
__device__ __forceinline__ float gelu_exact(float x){
    return 0.5f * x * (1.0f + erff(x * 0.70710678118654752440f));
}

// ---------------------------------------------------------------------------
// Weight prep: fp32 -> split-bf16, SW128 K-major tiles
__global__ void prep_w1(const float* __restrict__ w1){
    int n = blockIdx.x;            // 0..1023
    int k = threadIdx.x;           // 0..255
    float v = w1[n*256 + k];
    __nv_bfloat16 h = __float2bfloat16(v);
    __nv_bfloat16 l = __float2bfloat16(v - __bfloat162float(h));
    int nc = n >> 7, nl = n & 127, kt = k >> 6, kk = k & 63;
    size_t tbase = (size_t)(nc*4 + kt) * 32768u;
    uint32_t off = SWZ((uint32_t)(nl*128 + kk*2));
    *(__nv_bfloat16*)(g_w1 + tbase + off)         = h;
    *(__nv_bfloat16*)(g_w1 + tbase + 16384 + off) = l;
}
__global__ void prep_w2(const float* __restrict__ w2){
    int c = blockIdx.x;            // 0..255
    #pragma unroll
    for (int q = 0; q < 4; ++q){
        int k = threadIdx.x + q*256;   // 0..1023
        float v = w2[c*1024 + k];
        __nv_bfloat16 h = __float2bfloat16(v);
        __nv_bfloat16 l = __float2bfloat16(v - __bfloat162float(h));
        int nc = k >> 7, kt = (k >> 6) & 1, kk = k & 63;
        // stage index s = nc*4 + kt*2 + plane  (consumer j order: kt2=j>>1, p=j&1
        //  -> j = kt*2 + plane)
        size_t base_h = (size_t)(nc*4 + kt*2 + 0) * 32768u;
        size_t base_l = (size_t)(nc*4 + kt*2 + 1) * 32768u;
        uint32_t off = SWZ((uint32_t)(c*128 + kk*2));
        *(__nv_bfloat16*)(g_w2 + base_h + off) = h;
        *(__nv_bfloat16*)(g_w2 + base_l + off) = l;
    }
}

// ---------------------------------------------------------------------------
// adaLN modulation: mod = silu(c) @ ada_w.T + ada_b
__global__ void mod_kernel(const float* __restrict__ c_BD,
                           const float* __restrict__ ada_w,
                           const float* __restrict__ ada_b){
    __shared__ float sc[C_];
    int b   = blockIdx.x / 12;
    int grp = blockIdx.x % 12;
    int tid = threadIdx.x;
    float cv = c_BD[b*C_ + tid];
    sc[tid] = cv / (1.0f + expf(-cv));
    __syncthreads();
    int oo = grp*64 + (tid >> 2);
    int k0 = (tid & 3) * 64;
    const float* wr = ada_w + oo*C_ + k0;
    const float* ss = sc + k0;
    float s = 0.0f;
    #pragma unroll 8
    for (int k = 0; k < 64; ++k) s = fmaf(ss[k], wr[k], s);
    s += __shfl_xor_sync(0xffffffffu, s, 1);
    s += __shfl_xor_sync(0xffffffffu, s, 2);
    if ((tid & 3) == 0) g_mod[b][oo] = s + ada_b[oo];
}

// ---------------------------------------------------------------------------
// SMEM layout (bytes)
#define OFF_A    0u         // Ahi [64m x 512B]
#define OFF_ALO  32768u
#define OFF_W1   65536u     // 2 x 32KB ring
#define OFF_H1   131072u    // Hhi [64m x 256B]
#define OFF_H1LO 147456u
#define OFF_W2   163840u    // 2 x 32KB ring
#define OFF_IDX  229376u    // int[64]
#define OFF_MB   229632u    // 8 mbarriers
#define SMEM_BYTES 229696u

#define FW1(buf) (sb + OFF_MB +  0u + (uint32_t)(buf)*8u)
#define EW1(buf) (sb + OFF_MB + 16u + (uint32_t)(buf)*8u)
#define FW2(buf) (sb + OFF_MB + 32u + (uint32_t)(buf)*8u)
#define EW2(buf) (sb + OFF_MB + 48u + (uint32_t)(buf)*8u)
#define W1BUF(buf) (sb + OFF_W1 + (uint32_t)(buf)*32768u)
#define W2BUF(buf) (sb + OFF_W2 + (uint32_t)(buf)*32768u)

__global__ __launch_bounds__(256, 1)
void main_kernel(const float* __restrict__ x,
                 const float* __restrict__ bins,
                 const float* __restrict__ emb,
                 const float* __restrict__ pos,
                 const float* __restrict__ lng,
                 const float* __restrict__ lnb,
                 const float* __restrict__ b1,
                 const float* __restrict__ b2,
                 float* __restrict__ out){
    extern __shared__ __align__(1024) unsigned char smp[];
    const uint32_t sb = smem_u32(smp);
    const int tid  = threadIdx.x;
    const int warp = tid >> 5;
    const int lane = tid & 31;
    const int g    = lane >> 2;
    const int tg   = lane & 3;
    const int wm   = warp & 1;        // 2 warps in m
    const int wn   = warp >> 1;       // 4 warps in n

    const int t0 = blockIdx.x * TM;
    const int b  = t0 >> 16;
    const int ii = (t0 >> 8) & 255;
    const int j0 = t0 & 255;

    int* idxs = (int*)(smp + OFF_IDX);

    if (tid == 0){
        MBAR_INIT(FW1(0), 1); MBAR_INIT(FW1(1), 1);
        MBAR_INIT(EW1(0), 8); MBAR_INIT(EW1(1), 8);
        MBAR_INIT(FW2(0), 1); MBAR_INIT(FW2(1), 1);
        MBAR_INIT(EW2(0), 8); MBAR_INIT(EW2(1), 8);
    }
    __syncthreads();
    if (tid == 0){
        MBAR_EXPECT(FW1(0), 32768u); bulk_g2s(W1BUF(0), g_w1,          32768u, FW1(0));
        MBAR_EXPECT(FW1(1), 32768u); bulk_g2s(W1BUF(1), g_w1 + 32768u, 32768u, FW1(1));
        MBAR_EXPECT(FW2(0), 32768u); bulk_g2s(W2BUF(0), g_w2,          32768u, FW2(0));
        MBAR_EXPECT(FW2(1), 32768u); bulk_g2s(W2BUF(1), g_w2 + 32768u, 32768u, FW2(1));
    }

    // distance buckets for this tile's 64 tokens
    if (tid < TM){
        int j = j0 + tid;
        const float* xi = x + (b*L_ + ii)*3;
        const float* xj = x + (b*L_ + j )*3;
        float d0 = __fadd_rn(xi[0], -xj[0]);
        float d1 = __fadd_rn(xi[1], -xj[1]);
        float d2v = __fadd_rn(xi[2], -xj[2]);
        float d  = __fadd_rn(__fadd_rn(__fmul_rn(d0,d0), __fmul_rn(d1,d1)),
                             __fmul_rn(d2v,d2v));
        int cnt = 0;
        #pragma unroll
        for (int k = 0; k < 63; ++k) cnt += (bins[k] < d) ? 1 : 0;
        idxs[tid] = cnt;
    }
    __syncthreads();

    // ---- Phase 0: s -> modulate -> LN -> split bf16 into A ---------------
    {
        // hoist per-channel params (channels fixed per thread across rows)
        float2 sh2[4], sc2[4], lg2[4], lb2[4];
        #pragma unroll
        for (int q = 0; q < 4; ++q){
            int c0 = 2*lane + 64*q;
            sh2[q] = *(const float2*)(&g_mod[b][c0]);
            sc2[q] = *(const float2*)(&g_mod[b][C_ + c0]);
            lg2[q] = *(const float2*)(lng + c0);
            lb2[q] = *(const float2*)(lnb + c0);
        }
        for (int r = 0; r < 8; ++r){
            int m = warp*8 + r;
            int idv = idxs[m];
            int rel = ii - (j0 + m);
            rel = rel < -64 ? -64 : (rel > 63 ? 63 : rel);
            rel += 64;
            const float2* er = (const float2*)(emb + (idv << 8));
            const float2* pr = (const float2*)(pos + (rel << 8));
            float vx[4], vy[4];
            float sum = 0.0f;
            #pragma unroll
            for (int q = 0; q < 4; ++q){
                int c0 = 2*lane + 64*q;
                float2 e = er[c0 >> 1];
                float2 p = pr[c0 >> 1];
                float a0 = fmaf(e.x + p.x, 1.0f + sc2[q].x, sh2[q].x);
                float a1 = fmaf(e.y + p.y, 1.0f + sc2[q].y, sh2[q].y);
                vx[q] = a0; vy[q] = a1;
                sum += a0 + a1;
            }
            #pragma unroll
            for (int off = 16; off; off >>= 1)
                sum += __shfl_xor_sync(0xffffffffu, sum, off);
            float mu = sum * (1.0f/256.0f);
            float sq = 0.0f;
            #pragma unroll
            for (int q = 0; q < 4; ++q){
                float a0 = vx[q]-mu, a1 = vy[q]-mu;
                sq = fmaf(a0,a0, fmaf(a1,a1, sq));
            }
            #pragma unroll
            for (int off = 16; off; off >>= 1)
                sq += __shfl_xor_sync(0xffffffffu, sq, off);
            float rstd = rsqrtf(sq * (1.0f/256.0f) + LN_EPS);
            #pragma unroll
            for (int q = 0; q < 4; ++q){
                int c0 = 2*lane + 64*q;
                float h0 = fmaf((vx[q]-mu)*rstd, lg2[q].x, lb2[q].x);
                float h1 = fmaf((vy[q]-mu)*rstd, lg2[q].y, lb2[q].y);
                uint32_t hp, lp;
                split2(h0, h1, hp, lp);
                uint32_t so = sw_rowA(m, 2*c0);
                *(uint32_t*)(smp + OFF_A   + so) = hp;
                *(uint32_t*)(smp + OFF_ALO + so) = lp;
            }
        }
    }
    __syncthreads();

    float d2[2][8][4];
    #pragma unroll
    for (int a=0;a<2;++a)
        #pragma unroll
        for (int bb=0;bb<8;++bb)
            #pragma unroll
            for (int c=0;c<4;++c) d2[a][bb][c] = 0.0f;

    int phE1[2] = {0,0}, phE2[2] = {0,0};   // producer-side empty phases

    for (int nc = 0; nc < 8; ++nc){
        // prefetch fc1 bias values for this chunk (overlaps with GEMM1)
        float b1v[4][2];
        #pragma unroll
        for (int nt = 0; nt < 4; ++nt){
            int ncol = wn*32 + nt*8 + 2*tg;
            b1v[nt][0] = __ldg(b1 + nc*128 + ncol);
            b1v[nt][1] = __ldg(b1 + nc*128 + ncol + 1);
        }

        float c1[2][4][4];
        #pragma unroll
        for (int a=0;a<2;++a)
            #pragma unroll
            for (int bb=0;bb<4;++bb)
                #pragma unroll
                for (int c=0;c<4;++c) c1[a][bb][c] = 0.0f;

        // ---- GEMM1: 4 combined-plane stages of W1 ------------------------
        #pragma unroll 1
        for (int kt = 0; kt < 4; ++kt){
            const int s = nc*4 + kt, buf = s & 1;
            MBAR_WAIT(FW1(buf), (s>>1)&1);
            const uint32_t wb = W1BUF(buf);
            #pragma unroll
            for (int k4 = 0; k4 < 4; ++k4){
                const int kbW = k4*32 + ((lane>>3)&1)*16;
                const int kbA = kt*128 + k4*32 + (lane>>4)*16;
                uint32_t Bh[4][2], Bl[4][2];
                #pragma unroll
                for (int e = 0; e < 2; ++e){
                    uint32_t r4[4];
                    uint32_t ro = sw_row128(wn*32 + (2*e + (lane>>4))*8 + (lane&7), kbW);
                    ldsm4(r4, wb + ro);
                    Bh[2*e][0]=r4[0]; Bh[2*e][1]=r4[1]; Bh[2*e+1][0]=r4[2]; Bh[2*e+1][1]=r4[3];
                    ldsm4(r4, wb + 16384u + ro);
                    Bl[2*e][0]=r4[0]; Bl[2*e][1]=r4[1]; Bl[2*e+1][0]=r4[2]; Bl[2*e+1][1]=r4[3];
                }
                #pragma unroll
                for (int mt = 0; mt < 2; ++mt){
                    const int mrow = wm*32 + mt*16 + (lane&15);
                    uint32_t Ah[4], Al[4];
                    ldsm4(Ah, sb + OFF_A   + sw_rowA(mrow, kbA));
                    ldsm4(Al, sb + OFF_ALO + sw_rowA(mrow, kbA));
                    #pragma unroll
                    for (int nt = 0; nt < 4; ++nt) mma_bf16(c1[mt][nt], Ah, Bh[nt]);
                    #pragma unroll
                    for (int nt = 0; nt < 4; ++nt) mma_bf16(c1[mt][nt], Al, Bh[nt]);
                    #pragma unroll
                    for (int nt = 0; nt < 4; ++nt) mma_bf16(c1[mt][nt], Ah, Bl[nt]);
                }
            }
            if (lane == 0) MBAR_ARRIVE(EW1(buf));
            if (tid == 0){
                int s2 = s + 2;
                if (s2 < 32){
                    int b2i = s2 & 1;
                    MBAR_WAIT(EW1(b2i), phE1[b2i]); phE1[b2i] ^= 1;
                    MBAR_EXPECT(FW1(b2i), 32768u);
                    bulk_g2s(W1BUF(b2i), g_w1 + (size_t)s2*32768u, 32768u, FW1(b2i));
                }
            }
        }

        // ---- epilogue1: bias + gelu -> split -> H1 -----------------------
        #pragma unroll
        for (int mt = 0; mt < 2; ++mt){
            #pragma unroll
            for (int nt = 0; nt < 4; ++nt){
                const int ncol = wn*32 + nt*8 + 2*tg;
                #pragma unroll
                for (int half = 0; half < 2; ++half){
                    const int m = wm*32 + mt*16 + g + half*8;
                    float f0 = gelu_exact(c1[mt][nt][half*2+0] + b1v[nt][0]);
                    float f1 = gelu_exact(c1[mt][nt][half*2+1] + b1v[nt][1]);
                    uint32_t hp, lp;
                    split2(f0, f1, hp, lp);
                    uint32_t so = sw_rowH(m, 2*ncol);
                    *(uint32_t*)(smp + OFF_H1   + so) = hp;
                    *(uint32_t*)(smp + OFF_H1LO + so) = lp;
                }
            }
        }
        BARW(1 + wm);   // H1 writes visible within wm-half

        // ---- GEMM2: 4 single-plane stages of W2 --------------------------
        #pragma unroll 1
        for (int j = 0; j < 4; ++j){
            const int s = nc*4 + j, buf = s & 1;
            const int kt2 = j >> 1, p = j & 1;
            MBAR_WAIT(FW2(buf), (s>>1)&1);
            const uint32_t wb = W2BUF(buf);
            #pragma unroll
            for (int k4 = 0; k4 < 4; ++k4){
                const int kbW = k4*32 + ((lane>>3)&1)*16;
                const int kbH = kt2*128 + k4*32 + (lane>>4)*16;
                uint32_t Bf[8][2];
                #pragma unroll
                for (int e = 0; e < 4; ++e){
                    uint32_t r4[4];
                    uint32_t ro = sw_row128(wn*64 + (2*e + (lane>>4))*8 + (lane&7), kbW);
                    ldsm4(r4, wb + ro);
                    Bf[2*e][0]=r4[0]; Bf[2*e][1]=r4[1]; Bf[2*e+1][0]=r4[2]; Bf[2*e+1][1]=r4[3];
                }
                #pragma unroll
                for (int mt = 0; mt < 2; ++mt){
                    const int mrow = wm*32 + mt*16 + (lane&15);
                    uint32_t Hf[4];
                    ldsm4(Hf, sb + OFF_H1 + sw_rowH(mrow, kbH));
                    #pragma unroll
                    for (int nt = 0; nt < 8; ++nt) mma_bf16(d2[mt][nt], Hf, Bf[nt]);
                    if (p == 0){
                        ldsm4(Hf, sb + OFF_H1LO + sw_rowH(mrow, kbH));
                        #pragma unroll
                        for (int nt = 0; nt < 8; ++nt) mma_bf16(d2[mt][nt], Hf, Bf[nt]);
                    }
                }
            }
            if (lane == 0) MBAR_ARRIVE(EW2(buf));
            if (tid == 0){
                int s2 = s + 2;
                if (s2 < 32){
                    int b2i = s2 & 1;
                    MBAR_WAIT(EW2(b2i), phE2[b2i]); phE2[b2i] ^= 1;
                    MBAR_EXPECT(FW2(b2i), 32768u);
                    bulk_g2s(W2BUF(b2i), g_w2 + (size_t)s2*32768u, 32768u, FW2(b2i));
                }
            }
        }
        BARW(1 + wm);   // H1 consumed before next chunk overwrites
    }

    // ---- final epilogue: out = s + gate * (D2 + b2) ----------------------
    #pragma unroll
    for (int mt = 0; mt < 2; ++mt){
        #pragma unroll
        for (int half = 0; half < 2; ++half){
            const int m = wm*32 + mt*16 + g + half*8;
            const int t = t0 + m;
            const int idv = idxs[m];
            int rel = ii - (j0 + m);
            rel = rel < -64 ? -64 : (rel > 63 ? 63 : rel);
            rel += 64;
            const float* er = emb + (idv << 8);
            const float* pr = pos + (rel << 8);
            #pragma unroll
            for (int nt = 0; nt < 8; ++nt){
                const int c = wn*64 + nt*8 + 2*tg;
                float2 e2 = *(const float2*)(er + c);
                float2 p2 = *(const float2*)(pr + c);
                float2 sh2 = *(const float2*)(&g_mod[b][c]);
                float2 sc2 = *(const float2*)(&g_mod[b][C_ + c]);
                float2 gt2 = *(const float2*)(&g_mod[b][2*C_ + c]);
                float2 b22 = *(const float2*)(b2 + c);
                float s0 = fmaf(e2.x + p2.x, 1.0f + sc2.x, sh2.x);
                float s1 = fmaf(e2.y + p2.y, 1.0f + sc2.y, sh2.y);
                float2 o;
                o.x = fmaf(gt2.x, d2[mt][nt][half*2+0] + b22.x, s0);
                o.y = fmaf(gt2.y, d2[mt][nt][half*2+1] + b22.y, s1);
                *(float2*)(out + (size_t)t*256 + c) = o;
            }
        }
    }
    __syncthreads();
    if (tid == 0){
        MBAR_INVAL(FW1(0)); MBAR_INVAL(FW1(1));
        MBAR_INVAL(EW1(0)); MBAR_INVAL(EW1(1));
        MBAR_INVAL(FW2(0)); MBAR_INVAL(FW2(1));
        MBAR_INVAL(EW2(0)); MBAR_INVAL(EW2(1));
    }
}

// ---------------------------------------------------------------------------
extern "C" void kernel_launch(void* const* d_in, const int* in_sizes, int n_in,
                              void* d_out, int out_size) {
    const float* x     = (const float*)d_in[0];
    const float* c_BD  = (const float*)d_in[1];
    const float* emb   = (const float*)d_in[2];
    const float* pos   = (const float*)d_in[3];
    const float* bins  = (const float*)d_in[4];
    const float* ada_w = (const float*)d_in[5];
    const float* ada_b = (const float*)d_in[6];
    const float* ln_g  = (const float*)d_in[7];
    const float* ln_b  = (const float*)d_in[8];
    const float* fc1_w = (const float*)d_in[9];
    const float* fc1_b = (const float*)d_in[10];
    const float* fc2_w = (const float*)d_in[11];
    const float* fc2_b = (const float*)d_in[12];
    float* out = (float*)d_out;

    static bool attr_set = false;
    if (!attr_set){
        cudaFuncSetAttribute(main_kernel,
                             cudaFuncAttributeMaxDynamicSharedMemorySize, SMEM_BYTES);
        attr_set = true;
    }

    prep_w1<<<1024, 256>>>(fc1_w);
    prep_w2<<<256, 256>>>(fc2_w);
    mod_kernel<<<24, 256>>>(c_BD, ada_w, ada_b);
    main_kernel<<<NTOK/TM, 256, SMEM_BYTES>>>(x, bins, emb, pos, ln_g, ln_b,
                                              fc1_b, fc2_b, out);
}

// round 7
// speedup vs baseline: 4.3647x; 1.3882x over previous
#include <cuda_runtime.h>
#include <cuda_bf16.h>
#include <cuda_fp16.h>
#include <math.h>
#include <stdint.h>

// Problem constants
#define B_  2
#define L_  256
#define C_  256
#define NTOK (B_*L_*L_)
#define LN_EPS 1e-5f
#define TM 64            // tokens per CTA

// ---------------------------------------------------------------------------
// Device scratch (no cudaMalloc allowed)
__device__ __align__(16) float g_mod[B_][3*C_];
// W1 fp16 (hi only), SW128: stage s=nc*4+kt -> 16KB [128n x 64k]
__device__ __align__(16) unsigned char g_w1[524288];
// W2 fp16 (hi only), SW128: stage s=nc*2+kt -> 32KB [256c x 64k]
__device__ __align__(16) unsigned char g_w2[524288];

#define SWZ(o) ((o) ^ (((o)>>3)&0x70))

// ---------------------------------------------------------------------------
__device__ __forceinline__ uint32_t smem_u32(const void* p){
    uint32_t a;
    asm("{ .reg .u64 t; cvta.to.shared.u64 t, %1; cvt.u32.u64 %0, t; }"
        : "=r"(a) : "l"(p));
    return a;
}
#define MBAR_INIT(a,c) \
    asm volatile("mbarrier.init.shared.b64 [%0], %1;" :: "r"(a), "r"(c) : "memory")
#define MBAR_INVAL(a) \
    asm volatile("mbarrier.inval.shared.b64 [%0];" :: "r"(a) : "memory")
#define MBAR_EXPECT(a,tx) \
    asm volatile("mbarrier.arrive.expect_tx.shared.b64 _, [%0], %1;" :: "r"(a), "r"(tx) : "memory")
#define MBAR_ARRIVE(a) \
    asm volatile("mbarrier.arrive.shared.b64 _, [%0];" :: "r"(a) : "memory")
#define MBAR_WAIT(mb, ph) do{                                                   \
    uint32_t _m=(mb), _p=(ph), _d;                                              \
    asm volatile("{\n\t.reg .pred p;\n\t"                                       \
      "mbarrier.try_wait.parity.acquire.cta.shared::cta.b64 p, [%1], %2;\n\t"   \
      "selp.b32 %0,1,0,p;\n\t}" : "=r"(_d) : "r"(_m), "r"(_p) : "memory");      \
    while(!_d){                                                                 \
      asm volatile("{\n\t.reg .pred p;\n\t"                                     \
        "mbarrier.try_wait.parity.acquire.cta.shared::cta.b64 p, [%1], %2, 0x989680;\n\t" \
        "selp.b32 %0,1,0,p;\n\t}" : "=r"(_d) : "r"(_m), "r"(_p) : "memory"); }  \
}while(0)
#define BARW(id) asm volatile("bar.sync %0, 128;" :: "r"(id) : "memory")

__device__ __forceinline__ void bulk_g2s(uint32_t dst, const void* src,
                                         uint32_t bytes, uint32_t mbar){
    asm volatile("cp.async.bulk.shared::cluster.global.mbarrier::complete_tx::bytes "
                 "[%0], [%1], %2, [%3];"
                 :: "r"(dst), "l"(src), "r"(bytes), "r"(mbar) : "memory");
}

__device__ __forceinline__ void ldsm4(uint32_t* r, uint32_t a){
    asm volatile("ldmatrix.sync.aligned.m8n8.x4.shared.b16 {%0,%1,%2,%3}, [%4];"
        : "=r"(r[0]),"=r"(r[1]),"=r"(r[2]),"=r"(r[3]) : "r"(a));
}
__device__ __forceinline__ void mma_f16(float* c, const uint32_t* a, const uint32_t* b){
    asm volatile("mma.sync.aligned.m16n8k16.row.col.f32.f16.f16.f32 "
        "{%0,%1,%2,%3}, {%4,%5,%6,%7}, {%8,%9}, {%0,%1,%2,%3};"
        : "+f"(c[0]),"+f"(c[1]),"+f"(c[2]),"+f"(c[3])
        : "r"(a[0]),"r"(a[1]),"r"(a[2]),"r"(a[3]), "r"(b[0]),"r"(b[1]));
}

// swizzled row addressing (byte offsets)
__device__ __forceinline__ uint32_t sw_row128(int row, int kb){  // 128B rows
    return (uint32_t)(row*128 + (kb ^ ((row & 7) << 4)));
}
__device__ __forceinline__ uint32_t sw_rowA(int m, int kb){      // 512B rows
    return (uint32_t)(m*512 + ((kb & ~127) | ((kb & 127) ^ ((m & 7) << 4))));
}
__device__ __forceinline__ uint32_t sw_rowH(int m, int kb){      // 256B rows
    return (uint32_t)(m*256 + ((kb & ~127) | ((kb & 127) ^ ((m & 7) << 4))));
}

// split fp32 pair -> (hi,lo) packed f16x2
__device__ __forceinline__ void split2h(float a, float b, uint32_t& hi, uint32_t& lo){
    __half ha = __float2half_rn(a);
    __half hb = __float2half_rn(b);
    float ra = a - __half2float(ha);
    float rb = b - __half2float(hb);
    __half la = __float2half_rn(ra);
    __half lb = __float2half_rn(rb);
    hi = ((uint32_t)__half_as_ushort(hb) << 16) | __half_as_ushort(ha);
    lo = ((uint32_t)__half_as_ushort(lb) << 16) | __half_as_ushort(la);
}
__device__ __forceinline__ float gelu_exact(float x){
    return 0.5f * x * (1.0f + erff(x * 0.70710678118654752440f));
}

// ---------------------------------------------------------------------------
// Weight prep: fp32 -> fp16 (hi only), SW128 K-major tiles
__global__ void prep_w1(const float* __restrict__ w1){
    int n = blockIdx.x;            // 0..1023
    int k = threadIdx.x;           // 0..255
    float v = w1[n*256 + k];
    __half h = __float2half_rn(v);
    int nc = n >> 7, nl = n & 127, kt = k >> 6, kk = k & 63;
    size_t tbase = (size_t)(nc*4 + kt) * 16384u;
    uint32_t off = SWZ((uint32_t)(nl*128 + kk*2));
    *(__half*)(g_w1 + tbase + off) = h;
}
__global__ void prep_w2(const float* __restrict__ w2){
    int c = blockIdx.x;            // 0..255
    #pragma unroll
    for (int q = 0; q < 4; ++q){
        int k = threadIdx.x + q*256;   // 0..1023
        float v = w2[c*1024 + k];
        __half h = __float2half_rn(v);
        int nc = k >> 7, kt = (k >> 6) & 1, kk = k & 63;
        size_t tbase = (size_t)(nc*2 + kt) * 32768u;
        uint32_t off = SWZ((uint32_t)(c*128 + kk*2));
        *(__half*)(g_w2 + tbase + off) = h;
    }
}

// ---------------------------------------------------------------------------
// adaLN modulation: mod = silu(c) @ ada_w.T + ada_b
__global__ void mod_kernel(const float* __restrict__ c_BD,
                           const float* __restrict__ ada_w,
                           const float* __restrict__ ada_b){
    __shared__ float sc[C_];
    int b   = blockIdx.x / 12;
    int grp = blockIdx.x % 12;
    int tid = threadIdx.x;
    float cv = c_BD[b*C_ + tid];
    sc[tid] = cv / (1.0f + expf(-cv));
    __syncthreads();
    int oo = grp*64 + (tid >> 2);
    int k0 = (tid & 3) * 64;
    const float* wr = ada_w + oo*C_ + k0;
    const float* ss = sc + k0;
    float s = 0.0f;
    #pragma unroll 8
    for (int k = 0; k < 64; ++k) s = fmaf(ss[k], wr[k], s);
    s += __shfl_xor_sync(0xffffffffu, s, 1);
    s += __shfl_xor_sync(0xffffffffu, s, 2);
    if ((tid & 3) == 0) g_mod[b][oo] = s + ada_b[oo];
}

// ---------------------------------------------------------------------------
// SMEM layout (bytes)
#define OFF_A    0u         // Ahi [64m x 512B]
#define OFF_ALO  32768u
#define OFF_W1   65536u     // 2 x 16KB ring
#define OFF_H1   98304u     // Hhi [64m x 256B]
#define OFF_H1LO 114688u
#define OFF_W2   131072u    // 2 x 32KB ring
#define OFF_IDX  196608u    // int[64]
#define OFF_MB   196864u    // 8 mbarriers
#define SMEM_BYTES 196928u

#define FW1(buf) (sb + OFF_MB +  0u + (uint32_t)(buf)*8u)
#define EW1(buf) (sb + OFF_MB + 16u + (uint32_t)(buf)*8u)
#define FW2(buf) (sb + OFF_MB + 32u + (uint32_t)(buf)*8u)
#define EW2(buf) (sb + OFF_MB + 48u + (uint32_t)(buf)*8u)
#define W1BUF(buf) (sb + OFF_W1 + (uint32_t)(buf)*16384u)
#define W2BUF(buf) (sb + OFF_W2 + (uint32_t)(buf)*32768u)

__global__ __launch_bounds__(256, 1)
void main_kernel(const float* __restrict__ x,
                 const float* __restrict__ bins,
                 const float* __restrict__ emb,
                 const float* __restrict__ pos,
                 const float* __restrict__ lng,
                 const float* __restrict__ lnb,
                 const float* __restrict__ b1,
                 const float* __restrict__ b2,
                 float* __restrict__ out){
    extern __shared__ __align__(1024) unsigned char smp[];
    const uint32_t sb = smem_u32(smp);
    const int tid  = threadIdx.x;
    const int warp = tid >> 5;
    const int lane = tid & 31;
    const int g    = lane >> 2;
    const int tg   = lane & 3;
    const int wm   = warp & 1;        // 2 warps in m
    const int wn   = warp >> 1;       // 4 warps in n

    const int t0 = blockIdx.x * TM;
    const int b  = t0 >> 16;
    const int ii = (t0 >> 8) & 255;
    const int j0 = t0 & 255;

    int* idxs = (int*)(smp + OFF_IDX);

    if (tid == 0){
        MBAR_INIT(FW1(0), 1); MBAR_INIT(FW1(1), 1);
        MBAR_INIT(EW1(0), 8); MBAR_INIT(EW1(1), 8);
        MBAR_INIT(FW2(0), 1); MBAR_INIT(FW2(1), 1);
        MBAR_INIT(EW2(0), 8); MBAR_INIT(EW2(1), 8);
    }
    __syncthreads();
    if (tid == 0){
        MBAR_EXPECT(FW1(0), 16384u); bulk_g2s(W1BUF(0), g_w1,          16384u, FW1(0));
        MBAR_EXPECT(FW1(1), 16384u); bulk_g2s(W1BUF(1), g_w1 + 16384u, 16384u, FW1(1));
        MBAR_EXPECT(FW2(0), 32768u); bulk_g2s(W2BUF(0), g_w2,          32768u, FW2(0));
        MBAR_EXPECT(FW2(1), 32768u); bulk_g2s(W2BUF(1), g_w2 + 32768u, 32768u, FW2(1));
    }

    // distance buckets for this tile's 64 tokens
    if (tid < TM){
        int j = j0 + tid;
        const float* xi = x + (b*L_ + ii)*3;
        const float* xj = x + (b*L_ + j )*3;
        float d0 = __fadd_rn(xi[0], -xj[0]);
        float d1 = __fadd_rn(xi[1], -xj[1]);
        float d2v = __fadd_rn(xi[2], -xj[2]);
        float d  = __fadd_rn(__fadd_rn(__fmul_rn(d0,d0), __fmul_rn(d1,d1)),
                             __fmul_rn(d2v,d2v));
        int cnt = 0;
        #pragma unroll
        for (int k = 0; k < 63; ++k) cnt += (bins[k] < d) ? 1 : 0;
        idxs[tid] = cnt;
    }
    __syncthreads();

    // ---- Phase 0: s -> modulate -> LN -> split fp16 into A ---------------
    {
        float2 sh2[4], sc2[4], lg2[4], lb2[4];
        #pragma unroll
        for (int q = 0; q < 4; ++q){
            int c0 = 2*lane + 64*q;
            sh2[q] = *(const float2*)(&g_mod[b][c0]);
            sc2[q] = *(const float2*)(&g_mod[b][C_ + c0]);
            lg2[q] = *(const float2*)(lng + c0);
            lb2[q] = *(const float2*)(lnb + c0);
        }
        for (int r = 0; r < 8; ++r){
            int m = warp*8 + r;
            int idv = idxs[m];
            int rel = ii - (j0 + m);
            rel = rel < -64 ? -64 : (rel > 63 ? 63 : rel);
            rel += 64;
            const float2* er = (const float2*)(emb + (idv << 8));
            const float2* pr = (const float2*)(pos + (rel << 8));
            float vx[4], vy[4];
            float sum = 0.0f;
            #pragma unroll
            for (int q = 0; q < 4; ++q){
                int c0 = 2*lane + 64*q;
                float2 e = er[c0 >> 1];
                float2 p = pr[c0 >> 1];
                float a0 = fmaf(e.x + p.x, 1.0f + sc2[q].x, sh2[q].x);
                float a1 = fmaf(e.y + p.y, 1.0f + sc2[q].y, sh2[q].y);
                vx[q] = a0; vy[q] = a1;
                sum += a0 + a1;
            }
            #pragma unroll
            for (int off = 16; off; off >>= 1)
                sum += __shfl_xor_sync(0xffffffffu, sum, off);
            float mu = sum * (1.0f/256.0f);
            float sq = 0.0f;
            #pragma unroll
            for (int q = 0; q < 4; ++q){
                float a0 = vx[q]-mu, a1 = vy[q]-mu;
                sq = fmaf(a0,a0, fmaf(a1,a1, sq));
            }
            #pragma unroll
            for (int off = 16; off; off >>= 1)
                sq += __shfl_xor_sync(0xffffffffu, sq, off);
            float rstd = rsqrtf(sq * (1.0f/256.0f) + LN_EPS);
            #pragma unroll
            for (int q = 0; q < 4; ++q){
                int c0 = 2*lane + 64*q;
                float h0 = fmaf((vx[q]-mu)*rstd, lg2[q].x, lb2[q].x);
                float h1 = fmaf((vy[q]-mu)*rstd, lg2[q].y, lb2[q].y);
                uint32_t hp, lp;
                split2h(h0, h1, hp, lp);
                uint32_t so = sw_rowA(m, 2*c0);
                *(uint32_t*)(smp + OFF_A   + so) = hp;
                *(uint32_t*)(smp + OFF_ALO + so) = lp;
            }
        }
    }
    __syncthreads();

    float d2[2][8][4];
    #pragma unroll
    for (int a=0;a<2;++a)
        #pragma unroll
        for (int bb=0;bb<8;++bb)
            #pragma unroll
            for (int c=0;c<4;++c) d2[a][bb][c] = 0.0f;

    int phE1[2] = {0,0}, phE2[2] = {0,0};   // producer-side empty phases

    for (int nc = 0; nc < 8; ++nc){
        float b1v[4][2];
        #pragma unroll
        for (int nt = 0; nt < 4; ++nt){
            int ncol = wn*32 + nt*8 + 2*tg;
            b1v[nt][0] = __ldg(b1 + nc*128 + ncol);
            b1v[nt][1] = __ldg(b1 + nc*128 + ncol + 1);
        }

        float c1[2][4][4];
        #pragma unroll
        for (int a=0;a<2;++a)
            #pragma unroll
            for (int bb=0;bb<4;++bb)
                #pragma unroll
                for (int c=0;c<4;++c) c1[a][bb][c] = 0.0f;

        // ---- GEMM1: 4 stages of W1 (hi only, 16KB each) ------------------
        #pragma unroll 1
        for (int kt = 0; kt < 4; ++kt){
            const int s = nc*4 + kt, buf = s & 1;
            MBAR_WAIT(FW1(buf), (s>>1)&1);
            const uint32_t wb = W1BUF(buf);
            #pragma unroll
            for (int k4 = 0; k4 < 4; ++k4){
                const int kbW = k4*32 + ((lane>>3)&1)*16;
                const int kbA = kt*128 + k4*32 + (lane>>4)*16;
                uint32_t Bh[4][2];
                #pragma unroll
                for (int e = 0; e < 2; ++e){
                    uint32_t r4[4];
                    uint32_t ro = sw_row128(wn*32 + (2*e + (lane>>4))*8 + (lane&7), kbW);
                    ldsm4(r4, wb + ro);
                    Bh[2*e][0]=r4[0]; Bh[2*e][1]=r4[1]; Bh[2*e+1][0]=r4[2]; Bh[2*e+1][1]=r4[3];
                }
                #pragma unroll
                for (int mt = 0; mt < 2; ++mt){
                    const int mrow = wm*32 + mt*16 + (lane&15);
                    uint32_t Ah[4], Al[4];
                    ldsm4(Ah, sb + OFF_A   + sw_rowA(mrow, kbA));
                    ldsm4(Al, sb + OFF_ALO + sw_rowA(mrow, kbA));
                    #pragma unroll
                    for (int nt = 0; nt < 4; ++nt) mma_f16(c1[mt][nt], Ah, Bh[nt]);
                    #pragma unroll
                    for (int nt = 0; nt < 4; ++nt) mma_f16(c1[mt][nt], Al, Bh[nt]);
                }
            }
            if (lane == 0) MBAR_ARRIVE(EW1(buf));
            if (tid == 0){
                int s2 = s + 2;
                if (s2 < 32){
                    int b2i = s2 & 1;
                    MBAR_WAIT(EW1(b2i), phE1[b2i]); phE1[b2i] ^= 1;
                    MBAR_EXPECT(FW1(b2i), 16384u);
                    bulk_g2s(W1BUF(b2i), g_w1 + (size_t)s2*16384u, 16384u, FW1(b2i));
                }
            }
        }

        // ---- epilogue1: bias + gelu -> split -> H1 -----------------------
        #pragma unroll
        for (int mt = 0; mt < 2; ++mt){
            #pragma unroll
            for (int nt = 0; nt < 4; ++nt){
                const int ncol = wn*32 + nt*8 + 2*tg;
                #pragma unroll
                for (int half = 0; half < 2; ++half){
                    const int m = wm*32 + mt*16 + g + half*8;
                    float f0 = gelu_exact(c1[mt][nt][half*2+0] + b1v[nt][0]);
                    float f1 = gelu_exact(c1[mt][nt][half*2+1] + b1v[nt][1]);
                    uint32_t hp, lp;
                    split2h(f0, f1, hp, lp);
                    uint32_t so = sw_rowH(m, 2*ncol);
                    *(uint32_t*)(smp + OFF_H1   + so) = hp;
                    *(uint32_t*)(smp + OFF_H1LO + so) = lp;
                }
            }
        }
        BARW(1 + wm);   // H1 writes visible within wm-half

        // ---- GEMM2: 2 stages of W2 (hi only, 32KB each) ------------------
        #pragma unroll 1
        for (int kt2 = 0; kt2 < 2; ++kt2){
            const int s = nc*2 + kt2, buf = s & 1;
            MBAR_WAIT(FW2(buf), (s>>1)&1);
            const uint32_t wb = W2BUF(buf);
            #pragma unroll
            for (int k4 = 0; k4 < 4; ++k4){
                const int kbW = k4*32 + ((lane>>3)&1)*16;
                const int kbH = kt2*128 + k4*32 + (lane>>4)*16;
                uint32_t Bf[8][2];
                #pragma unroll
                for (int e = 0; e < 4; ++e){
                    uint32_t r4[4];
                    uint32_t ro = sw_row128(wn*64 + (2*e + (lane>>4))*8 + (lane&7), kbW);
                    ldsm4(r4, wb + ro);
                    Bf[2*e][0]=r4[0]; Bf[2*e][1]=r4[1]; Bf[2*e+1][0]=r4[2]; Bf[2*e+1][1]=r4[3];
                }
                #pragma unroll
                for (int mt = 0; mt < 2; ++mt){
                    const int mrow = wm*32 + mt*16 + (lane&15);
                    uint32_t Hh[4], Hl[4];
                    ldsm4(Hh, sb + OFF_H1   + sw_rowH(mrow, kbH));
                    ldsm4(Hl, sb + OFF_H1LO + sw_rowH(mrow, kbH));
                    #pragma unroll
                    for (int nt = 0; nt < 8; ++nt) mma_f16(d2[mt][nt], Hh, Bf[nt]);
                    #pragma unroll
                    for (int nt = 0; nt < 8; ++nt) mma_f16(d2[mt][nt], Hl, Bf[nt]);
                }
            }
            if (lane == 0) MBAR_ARRIVE(EW2(buf));
            if (tid == 0){
                int s2 = s + 2;
                if (s2 < 16){
                    int b2i = s2 & 1;
                    MBAR_WAIT(EW2(b2i), phE2[b2i]); phE2[b2i] ^= 1;
                    MBAR_EXPECT(FW2(b2i), 32768u);
                    bulk_g2s(W2BUF(b2i), g_w2 + (size_t)s2*32768u, 32768u, FW2(b2i));
                }
            }
        }
        BARW(1 + wm);   // H1 consumed before next chunk overwrites
    }

    // ---- final epilogue: out = s + gate * (D2 + b2) ----------------------
    #pragma unroll
    for (int mt = 0; mt < 2; ++mt){
        #pragma unroll
        for (int half = 0; half < 2; ++half){
            const int m = wm*32 + mt*16 + g + half*8;
            const int t = t0 + m;
            const int idv = idxs[m];
            int rel = ii - (j0 + m);
            rel = rel < -64 ? -64 : (rel > 63 ? 63 : rel);
            rel += 64;
            const float* er = emb + (idv << 8);
            const float* pr = pos + (rel << 8);
            #pragma unroll
            for (int nt = 0; nt < 8; ++nt){
                const int c = wn*64 + nt*8 + 2*tg;
                float2 e2 = *(const float2*)(er + c);
                float2 p2 = *(const float2*)(pr + c);
                float2 sh2 = *(const float2*)(&g_mod[b][c]);
                float2 sc2 = *(const float2*)(&g_mod[b][C_ + c]);
                float2 gt2 = *(const float2*)(&g_mod[b][2*C_ + c]);
                float2 b22 = *(const float2*)(b2 + c);
                float s0 = fmaf(e2.x + p2.x, 1.0f + sc2.x, sh2.x);
                float s1 = fmaf(e2.y + p2.y, 1.0f + sc2.y, sh2.y);
                float2 o;
                o.x = fmaf(gt2.x, d2[mt][nt][half*2+0] + b22.x, s0);
                o.y = fmaf(gt2.y, d2[mt][nt][half*2+1] + b22.y, s1);
                *(float2*)(out + (size_t)t*256 + c) = o;
            }
        }
    }
    __syncthreads();
    if (tid == 0){
        MBAR_INVAL(FW1(0)); MBAR_INVAL(FW1(1));
        MBAR_INVAL(EW1(0)); MBAR_INVAL(EW1(1));
        MBAR_INVAL(FW2(0)); MBAR_INVAL(FW2(1));
        MBAR_INVAL(EW2(0)); MBAR_INVAL(EW2(1));
    }
}

// ---------------------------------------------------------------------------
extern "C" void kernel_launch(void* const* d_in, const int* in_sizes, int n_in,
                              void* d_out, int out_size) {
    const float* x     = (const float*)d_in[0];
    const float* c_BD  = (const float*)d_in[1];
    const float* emb   = (const float*)d_in[2];
    const float* pos   = (const float*)d_in[3];
    const float* bins  = (const float*)d_in[4];
    const float* ada_w = (const float*)d_in[5];
    const float* ada_b = (const float*)d_in[6];
    const float* ln_g  = (const float*)d_in[7];
    const float* ln_b  = (const float*)d_in[8];
    const float* fc1_w = (const float*)d_in[9];
    const float* fc1_b = (const float*)d_in[10];
    const float* fc2_w = (const float*)d_in[11];
    const float* fc2_b = (const float*)d_in[12];
    float* out = (float*)d_out;

    static bool attr_set = false;
    if (!attr_set){
        cudaFuncSetAttribute(main_kernel,
                             cudaFuncAttributeMaxDynamicSharedMemorySize, SMEM_BYTES);
        attr_set = true;
    }

    prep_w1<<<1024, 256>>>(fc1_w);
    prep_w2<<<256, 256>>>(fc2_w);
    mod_kernel<<<24, 256>>>(c_BD, ada_w, ada_b);
    main_kernel<<<NTOK/TM, 256, SMEM_BYTES>>>(x, bins, emb, pos, ln_g, ln_b,
                                              fc1_b, fc2_b, out);
}